// round 11
// baseline (speedup 1.0000x reference)
#include <cuda_runtime.h>
#include <cuda_fp16.h>
#include <cstdint>

// Problem constants
#define BDIM 2
#define LSEQ 8192
#define CDIM 512
#define KWIN 17
#define HALFK 8
#define NTOK (BDIM * LSEQ)      // 16384

// ---------------------------------------------------------------------------
// Scratch (__device__ globals; no cudaMalloc allowed)
// ---------------------------------------------------------------------------
__device__ __half  g_qkvh[(size_t)NTOK * 3 * CDIM];    // 48 MB fp16 qkv
__device__ __half  g_xh[(size_t)NTOK * CDIM];          // x   -> fp16
__device__ __half  g_ah[(size_t)NTOK * CDIM];          // att -> fp16
__device__ __half  g_wqh[(size_t)3 * CDIM * CDIM];     // w_qkv^T fp16
__device__ __half  g_woh[(size_t)CDIM * CDIM];         // w_out^T fp16

// ---------------------------------------------------------------------------
// helpers
// ---------------------------------------------------------------------------
__device__ __forceinline__ uint32_t smem_u32(const void* p) {
    uint32_t a;
    asm("{ .reg .u64 t; cvta.to.shared.u64 t, %1; cvt.u32.u64 %0, t; }" : "=r"(a) : "l"(p));
    return a;
}
__device__ __forceinline__ void cp16(uint32_t dst, const void* src) {
    asm volatile("cp.async.cg.shared.global [%0], [%1], 16;" :: "r"(dst), "l"(src));
}
__device__ __forceinline__ void ldsm_x4(uint32_t* r, uint32_t addr) {
    asm volatile("ldmatrix.sync.aligned.m8n8.x4.shared.b16 {%0,%1,%2,%3}, [%4];"
                 : "=r"(r[0]), "=r"(r[1]), "=r"(r[2]), "=r"(r[3]) : "r"(addr));
}
__device__ __forceinline__ void ldsm_x2(uint32_t* r, uint32_t addr) {
    asm volatile("ldmatrix.sync.aligned.m8n8.x2.shared.b16 {%0,%1}, [%2];"
                 : "=r"(r[0]), "=r"(r[1]) : "r"(addr));
}
__device__ __forceinline__ void mma_f16(float* c, const uint32_t* a, const uint32_t* b) {
    asm volatile(
        "mma.sync.aligned.m16n8k16.row.col.f32.f16.f16.f32 "
        "{%0,%1,%2,%3}, {%4,%5,%6,%7}, {%8,%9}, {%0,%1,%2,%3};"
        : "+f"(c[0]), "+f"(c[1]), "+f"(c[2]), "+f"(c[3])
        : "r"(a[0]), "r"(a[1]), "r"(a[2]), "r"(a[3]), "r"(b[0]), "r"(b[1]));
}
#define CPWAIT(N) asm volatile("cp.async.wait_group %0;" :: "n"(N))

__device__ __forceinline__ void unpack8(uint4 u, float* f) {
    const __half2* h = (const __half2*)&u;
    #pragma unroll
    for (int t = 0; t < 4; t++) {
        float2 v = __half22float2(h[t]);
        f[2 * t] = v.x;
        f[2 * t + 1] = v.y;
    }
}

// ---------------------------------------------------------------------------
// Plain fp16 GEMM:  C = A @ B^T  (fp32 accum, OutT store)
// Block 128x128, 8 warps (2x4), warp 64x32.  BK=128 stages (4 total), double
// buffered cp.async; 1 CTA/SM (smem-forced) -> regs free for explicit
// fragment double-buffering (ldsm for kk+1 overlaps MMAs of kk).
// PITCH=272 -> conflict-free ldmatrix (68 words == 4 mod 32).
// ---------------------------------------------------------------------------
#define GK       512
#define BK       128
#define NSTG     (GK / BK)          // 4
#define PITCH    272                // 256B data + 16B pad
#define A_SZ     (128 * PITCH)      // 34816
#define STG_SZ   (2 * A_SZ)         // A | B = 69632
#define GEMM_SMEM (2 * STG_SZ)      // 139264  -> 1 CTA/SM

template <typename OutT>
__global__ __launch_bounds__(256) void gemm_mma(
    const __half* __restrict__ A, const __half* __restrict__ B,
    OutT* __restrict__ C, int Ntot)
{
    extern __shared__ char smem[];
    const uint32_t sb = smem_u32(smem);
    const int tid  = threadIdx.x;
    const int wid  = tid >> 5;
    const int lane = tid & 31;
    const int bm = blockIdx.y * 128;
    const int bn = blockIdx.x * 128;
    const int warp_m = (wid >> 2) * 64;
    const int warp_n = (wid & 3) * 32;

    // loader: 128 rows x 16 chunks(16B) per matrix = 2048 chunks / 256 thr
    auto load_stage = [&](int s, int b) {
        const int k0 = s * BK;
        const uint32_t buf = sb + (uint32_t)b * STG_SZ;
        #pragma unroll
        for (int r = 0; r < 8; r++) {
            const int i   = tid + 256 * r;
            const int row = i >> 4;
            const int c16 = (i & 15) * 16;
            const uint32_t off = (uint32_t)(row * PITCH + c16);
            cp16(buf + off,        A + (size_t)(bm + row) * GK + k0 + (c16 >> 1));
            cp16(buf + A_SZ + off, B + (size_t)(bn + row) * GK + k0 + (c16 >> 1));
        }
        asm volatile("cp.async.commit_group;" ::: "memory");
    };

    float acc[4][4][4];
    #pragma unroll
    for (int mi = 0; mi < 4; mi++)
        #pragma unroll
        for (int ni = 0; ni < 4; ni++)
            #pragma unroll
            for (int f = 0; f < 4; f++) acc[mi][ni][f] = 0.f;

    const uint32_t aLane = (uint32_t)((warp_m + (lane & 15)) * PITCH + ((lane >> 4) & 1) * 16);
    const uint32_t bLane = (uint32_t)((warp_n + (lane & 7)) * PITCH + ((lane >> 3) & 1) * 16);

    load_stage(0, 0);
    load_stage(1, 1);

    // fragment double buffers
    uint32_t ah[2][4][4], bh[2][4][2];

    for (int s = 0; s < NSTG; s++) {
        const int b = s & 1;
        if (s + 1 < NSTG) CPWAIT(1);
        else              CPWAIT(0);
        __syncthreads();

        const uint32_t buf = sb + (uint32_t)b * STG_SZ;

        // prime kk=0 frags
        #pragma unroll
        for (int mi = 0; mi < 4; mi++)
            ldsm_x4(ah[0][mi], buf + aLane + (uint32_t)(mi * 16 * PITCH));
        #pragma unroll
        for (int ni = 0; ni < 4; ni++)
            ldsm_x2(bh[0][ni], buf + A_SZ + bLane + (uint32_t)(ni * 8 * PITCH));

        #pragma unroll
        for (int kk = 0; kk < 8; kk++) {           // eight k16 steps per stage
            const int cur = kk & 1;
            const int nxt = cur ^ 1;
            if (kk < 7) {                          // prefetch kk+1 frags
                const uint32_t ko = (uint32_t)((kk + 1) * 32);
                #pragma unroll
                for (int mi = 0; mi < 4; mi++)
                    ldsm_x4(ah[nxt][mi], buf + aLane + (uint32_t)(mi * 16 * PITCH) + ko);
                #pragma unroll
                for (int ni = 0; ni < 4; ni++)
                    ldsm_x2(bh[nxt][ni], buf + A_SZ + bLane + (uint32_t)(ni * 8 * PITCH) + ko);
            }
            #pragma unroll
            for (int mi = 0; mi < 4; mi++)
                #pragma unroll
                for (int ni = 0; ni < 4; ni++)
                    mma_f16(acc[mi][ni], ah[cur][mi], bh[cur][ni]);
        }
        __syncthreads();
        if (s + 2 < NSTG) load_stage(s + 2, b);
    }

    const int er = lane >> 2;
    const int ec = (lane & 3) * 2;
    #pragma unroll
    for (int mi = 0; mi < 4; mi++) {
        #pragma unroll
        for (int ni = 0; ni < 4; ni++) {
            OutT* p0 = C + (size_t)(bm + warp_m + mi * 16 + er) * Ntot + bn + warp_n + ni * 8 + ec;
            if constexpr (sizeof(OutT) == 2) {
                *(__half2*)p0 = __floats2half2_rn(acc[mi][ni][0], acc[mi][ni][1]);
                *(__half2*)(p0 + (size_t)8 * Ntot) = __floats2half2_rn(acc[mi][ni][2], acc[mi][ni][3]);
            } else {
                *(float2*)p0                      = make_float2(acc[mi][ni][0], acc[mi][ni][1]);
                *(float2*)(p0 + (size_t)8 * Ntot) = make_float2(acc[mi][ni][2], acc[mi][ni][3]);
            }
        }
    }
}

// ---------------------------------------------------------------------------
// fused prep: x->fp16 (blocks 0..8191), w_qkv^T (next 768), w_out^T (next 256)
// ---------------------------------------------------------------------------
__global__ __launch_bounds__(256) void prep_kernel(
    const float* __restrict__ x,     __half* __restrict__ xh,
    const float* __restrict__ wq,    __half* __restrict__ wqh,
    const float* __restrict__ wo,    __half* __restrict__ woh)
{
    const int bid = blockIdx.x;
    const int tid = threadIdx.x;
    if (bid < 8192) {
        const size_t i = ((size_t)bid * 256 + tid) * 4;
        float4 v = *(const float4*)(x + i);
        *(__half2*)(xh + i)     = __floats2half2_rn(v.x, v.y);
        *(__half2*)(xh + i + 2) = __floats2half2_rn(v.z, v.w);
        return;
    }
    __shared__ float t[32][33];
    const float* w;  __half* wT;  int N, bx, by;
    if (bid < 8192 + 768) {          // w_qkv: [512,1536], grid (48,16)
        w = wq; wT = wqh; N = 3 * CDIM;
        const int r = bid - 8192;
        bx = r % 48; by = r / 48;
    } else {                          // w_out: [512,512], grid (16,16)
        w = wo; wT = woh; N = CDIM;
        const int r = bid - 8960;
        bx = r % 16; by = r / 16;
    }
    const int k0 = by * 32;
    const int n0 = bx * 32;
    const int tx = tid & 31, ty = tid >> 5;     // 32 x 8
    #pragma unroll
    for (int i = ty; i < 32; i += 8)
        t[i][tx] = w[(size_t)(k0 + i) * N + n0 + tx];
    __syncthreads();
    #pragma unroll
    for (int i = ty; i < 32; i += 8)
        wT[(size_t)(n0 + i) * CDIM + k0 + tx] = __float2half(t[tx][i]);
}

// ---------------------------------------------------------------------------
// Warp-per-token windowed attention over fp16 qkv; fp16 output
// ---------------------------------------------------------------------------
__global__ __launch_bounds__(256) void attn_kernel(const float* __restrict__ x,
                                                   const float* __restrict__ w_width,
                                                   const float* __restrict__ b_width,
                                                   __half* __restrict__ att)
{
    const int gwarp = (blockIdx.x * blockDim.x + threadIdx.x) >> 5;
    const int lane = threadIdx.x & 31;
    if (gwarp >= NTOK) return;

    const int b = gwarp >> 13;
    const int l = gwarp & (LSEQ - 1);

    const __half* qkv = g_qkvh;

    float q[16];
    {
        const uint4* q4 = (const uint4*)(qkv + (size_t)gwarp * 3 * CDIM);
        #pragma unroll
        for (int i = 0; i < 2; i++) unpack8(q4[lane + 32 * i], q + 8 * i);
    }

    const float4* x4 = (const float4*)(x + (size_t)gwarp * CDIM);
    const float4* w4 = (const float4*)w_width;
    float wsum = 0.f;
    #pragma unroll
    for (int i = 0; i < 4; i++) {
        const float4 xv = x4[lane + 32 * i];
        const float4 wv = w4[lane + 32 * i];
        wsum += xv.x * wv.x + xv.y * wv.y + xv.z * wv.z + xv.w * wv.w;
    }
    #pragma unroll
    for (int o = 16; o > 0; o >>= 1) wsum += __shfl_xor_sync(0xffffffffu, wsum, o);
    const float width = 1.f / (1.f + expf(-(wsum + b_width[0]))) * (float)(KWIN - 1) + 1.f;

    float sc[KWIN];
    #pragma unroll
    for (int j = 0; j < KWIN; j++) {
        const int row = l + j - HALFK;
        float s = 0.f;
        if (row >= 0 && row < LSEQ) {
            const uint4* k4 = (const uint4*)(qkv + ((size_t)(b * LSEQ + row) * 3 + 1) * CDIM);
            #pragma unroll
            for (int i = 0; i < 2; i++) {
                float kf[8];
                unpack8(k4[lane + 32 * i], kf);
                #pragma unroll
                for (int t = 0; t < 8; t++) s += q[8 * i + t] * kf[t];
            }
        }
        #pragma unroll
        for (int o = 16; o > 0; o >>= 1) s += __shfl_xor_sync(0xffffffffu, s, o);
        sc[j] = s;
    }

    const float scale = 0.044194173824159216f;
    float mx = -1e30f;
    #pragma unroll
    for (int j = 0; j < KWIN; j++) {
        const float rel = fabsf((float)j - (float)HALFK);
        const float m = 1.f / (1.f + expf(-(width - rel) * 5.f));
        sc[j] = sc[j] * scale - (1.f - m) * 10000.f;
        mx = fmaxf(mx, sc[j]);
    }
    float denom = 0.f;
    #pragma unroll
    for (int j = 0; j < KWIN; j++) {
        sc[j] = expf(sc[j] - mx);
        denom += sc[j];
    }
    const float inv = 1.f / denom;

    float acc[16];
    {
        const uint4* vs = (const uint4*)(qkv + ((size_t)gwarp * 3 + 2) * CDIM);
        #pragma unroll
        for (int i = 0; i < 2; i++) unpack8(vs[lane + 32 * i], acc + 8 * i);
    }

    #pragma unroll
    for (int j = 0; j < KWIN; j++) {
        const int row = l + j - HALFK;
        if (row < 0 || row >= LSEQ) continue;
        const float a = sc[j] * inv;
        const uint4* v4 = (const uint4*)(qkv + ((size_t)(b * LSEQ + row) * 3 + 2) * CDIM);
        #pragma unroll
        for (int i = 0; i < 2; i++) {
            float vf[8];
            unpack8(v4[lane + 32 * i], vf);
            #pragma unroll
            for (int t = 0; t < 8; t++) acc[8 * i + t] += a * vf[t];
        }
    }

    uint4* arow = (uint4*)(att + (size_t)gwarp * CDIM);
    #pragma unroll
    for (int i = 0; i < 2; i++) {
        uint4 uh;
        __half2* hh = (__half2*)&uh;
        #pragma unroll
        for (int t = 0; t < 4; t++)
            hh[t] = __floats2half2_rn(acc[8 * i + 2 * t], acc[8 * i + 2 * t + 1]);
        arow[lane + 32 * i] = uh;
    }
}

// ---------------------------------------------------------------------------
extern "C" void kernel_launch(void* const* d_in, const int* in_sizes, int n_in,
                              void* d_out, int out_size)
{
    const float* x       = (const float*)d_in[0];
    const float* w_qkv   = (const float*)d_in[1];
    const float* w_width = (const float*)d_in[2];
    const float* b_width = (const float*)d_in[3];
    const float* w_out   = (const float*)d_in[4];
    float* out = (float*)d_out;

    __half* qkvh; cudaGetSymbolAddress((void**)&qkvh, g_qkvh);
    __half* xh;   cudaGetSymbolAddress((void**)&xh,   g_xh);
    __half* ah;   cudaGetSymbolAddress((void**)&ah,   g_ah);
    __half* wqh;  cudaGetSymbolAddress((void**)&wqh,  g_wqh);
    __half* woh;  cudaGetSymbolAddress((void**)&woh,  g_woh);

    cudaFuncSetAttribute(gemm_mma<__half>, cudaFuncAttributeMaxDynamicSharedMemorySize, GEMM_SMEM);
    cudaFuncSetAttribute(gemm_mma<float>,  cudaFuncAttributeMaxDynamicSharedMemorySize, GEMM_SMEM);

    // 0) fused prep: x->fp16 + both weight transposes
    prep_kernel<<<8192 + 768 + 256, 256>>>(x, xh, w_qkv, wqh, w_out, woh);

    // 1) qkv = x @ w_qkv   (fp16 in, fp16 out)
    {
        dim3 grid(3 * CDIM / 128, NTOK / 128);
        gemm_mma<__half><<<grid, 256, GEMM_SMEM>>>(xh, wqh, qkvh, 3 * CDIM);
    }

    // 2) fused windowed attention (fp16 qkv) -> att (fp16)
    attn_kernel<<<NTOK / 8, 256>>>(x, w_width, b_width, ah);

    // 3) out = att @ w_out  (fp16 in, fp32 out)
    {
        dim3 grid(CDIM / 128, NTOK / 128);
        gemm_mma<float><<<grid, 256, GEMM_SMEM>>>(ah, woh, out, CDIM);
    }
}

// round 12
// speedup vs baseline: 1.1766x; 1.1766x over previous
#include <cuda_runtime.h>
#include <cuda_fp16.h>
#include <cstdint>

// Problem constants
#define BDIM 2
#define LSEQ 8192
#define CDIM 512
#define KWIN 17
#define HALFK 8
#define NTOK (BDIM * LSEQ)      // 16384

// ---------------------------------------------------------------------------
// Scratch (__device__ globals; no cudaMalloc allowed)
// ---------------------------------------------------------------------------
__device__ __half  g_qkvh[(size_t)NTOK * 3 * CDIM];    // 48 MB fp16 qkv
__device__ __half  g_xh[(size_t)NTOK * CDIM];          // x   -> fp16
__device__ __half  g_ah[(size_t)NTOK * CDIM];          // att -> fp16
__device__ __half  g_wqh[(size_t)3 * CDIM * CDIM];     // w_qkv^T fp16
__device__ __half  g_woh[(size_t)CDIM * CDIM];         // w_out^T fp16

// ---------------------------------------------------------------------------
// helpers
// ---------------------------------------------------------------------------
__device__ __forceinline__ uint32_t smem_u32(const void* p) {
    uint32_t a;
    asm("{ .reg .u64 t; cvta.to.shared.u64 t, %1; cvt.u32.u64 %0, t; }" : "=r"(a) : "l"(p));
    return a;
}
__device__ __forceinline__ void cp16(uint32_t dst, const void* src) {
    asm volatile("cp.async.cg.shared.global [%0], [%1], 16;" :: "r"(dst), "l"(src));
}
__device__ __forceinline__ void ldsm_x4(uint32_t* r, uint32_t addr) {
    asm volatile("ldmatrix.sync.aligned.m8n8.x4.shared.b16 {%0,%1,%2,%3}, [%4];"
                 : "=r"(r[0]), "=r"(r[1]), "=r"(r[2]), "=r"(r[3]) : "r"(addr));
}
__device__ __forceinline__ void ldsm_x2(uint32_t* r, uint32_t addr) {
    asm volatile("ldmatrix.sync.aligned.m8n8.x2.shared.b16 {%0,%1}, [%2];"
                 : "=r"(r[0]), "=r"(r[1]) : "r"(addr));
}
__device__ __forceinline__ void mma_f16(float* c, const uint32_t* a, const uint32_t* b) {
    asm volatile(
        "mma.sync.aligned.m16n8k16.row.col.f32.f16.f16.f32 "
        "{%0,%1,%2,%3}, {%4,%5,%6,%7}, {%8,%9}, {%0,%1,%2,%3};"
        : "+f"(c[0]), "+f"(c[1]), "+f"(c[2]), "+f"(c[3])
        : "r"(a[0]), "r"(a[1]), "r"(a[2]), "r"(a[3]), "r"(b[0]), "r"(b[1]));
}
#define CPWAIT(N) asm volatile("cp.async.wait_group %0;" :: "n"(N))

__device__ __forceinline__ void unpack8(uint4 u, float* f) {
    const __half2* h = (const __half2*)&u;
    #pragma unroll
    for (int t = 0; t < 4; t++) {
        float2 v = __half22float2(h[t]);
        f[2 * t] = v.x;
        f[2 * t + 1] = v.y;
    }
}

// ---------------------------------------------------------------------------
// Plain fp16 GEMM:  C = A @ B^T  (fp32 accum, OutT store)
// Block 128x128, 8 warps (2x4), warp 64x32.  BK=64 stages, 3 buffers,
// ONE __syncthreads per stage.  cp.async for stage s+2 issues AFTER the MMA
// loop (R8 evidence: early LSU burst delays the ldsm/MMA ramp).  2 CTAs/SM.
// PITCH=144 -> conflict-free ldmatrix.
// ---------------------------------------------------------------------------
#define GK       512
#define BK       64
#define NSTG     (GK / BK)          // 8
#define NBUF     3
#define PITCH    144
#define A_SZ     (128 * PITCH)      // 18432
#define STG_SZ   (2 * A_SZ)         // A | B = 36864
#define GEMM_SMEM (NBUF * STG_SZ)   // 110592

template <typename OutT>
__global__ __launch_bounds__(256, 2) void gemm_mma(
    const __half* __restrict__ A, const __half* __restrict__ B,
    OutT* __restrict__ C, int Ntot)
{
    extern __shared__ char smem[];
    const uint32_t sb = smem_u32(smem);
    const int tid  = threadIdx.x;
    const int wid  = tid >> 5;
    const int lane = tid & 31;
    const int bm = blockIdx.y * 128;
    const int bn = blockIdx.x * 128;
    const int warp_m = (wid >> 2) * 64;
    const int warp_n = (wid & 3) * 32;

    auto load_stage = [&](int s, int b) {
        const int k0 = s * BK;
        const uint32_t buf = sb + (uint32_t)b * STG_SZ;
        #pragma unroll
        for (int r = 0; r < 4; r++) {
            const int i   = tid + 256 * r;
            const int row = i >> 3;
            const int c16 = (i & 7) * 16;
            const uint32_t off = (uint32_t)(row * PITCH + c16);
            cp16(buf + off,        A + (size_t)(bm + row) * GK + k0 + (c16 >> 1));
            cp16(buf + A_SZ + off, B + (size_t)(bn + row) * GK + k0 + (c16 >> 1));
        }
        asm volatile("cp.async.commit_group;" ::: "memory");
    };

    float acc[4][4][4];
    #pragma unroll
    for (int mi = 0; mi < 4; mi++)
        #pragma unroll
        for (int ni = 0; ni < 4; ni++)
            #pragma unroll
            for (int f = 0; f < 4; f++) acc[mi][ni][f] = 0.f;

    const uint32_t aLane = (uint32_t)((warp_m + (lane & 15)) * PITCH + ((lane >> 4) & 1) * 16);
    const uint32_t bLane = (uint32_t)((warp_n + (lane & 7)) * PITCH + ((lane >> 3) & 1) * 16);

    load_stage(0, 0);
    load_stage(1, 1);

    for (int s = 0; s < NSTG; s++) {
        const int b = s % NBUF;
        if (s + 1 < NSTG) CPWAIT(1);
        else              CPWAIT(0);
        __syncthreads();

        const uint32_t buf = sb + (uint32_t)b * STG_SZ;
        #pragma unroll
        for (int kk = 0; kk < 4; kk++) {
            const uint32_t ko = (uint32_t)(kk * 32);
            uint32_t ah[4][4], bh[4][2];
            #pragma unroll
            for (int mi = 0; mi < 4; mi++)
                ldsm_x4(ah[mi], buf + aLane + (uint32_t)(mi * 16 * PITCH) + ko);
            #pragma unroll
            for (int ni = 0; ni < 4; ni++)
                ldsm_x2(bh[ni], buf + A_SZ + bLane + (uint32_t)(ni * 8 * PITCH) + ko);
            #pragma unroll
            for (int mi = 0; mi < 4; mi++)
                #pragma unroll
                for (int ni = 0; ni < 4; ni++)
                    mma_f16(acc[mi][ni], ah[mi], bh[ni]);
        }

        // issue the s+2 loads AFTER compute: target buffer (s+2)%3 == (s-1)%3
        // was consumed at stage s-1; the top-of-stage barrier covered it.
        if (s + 2 < NSTG) load_stage(s + 2, (s + 2) % NBUF);
    }

    const int er = lane >> 2;
    const int ec = (lane & 3) * 2;
    #pragma unroll
    for (int mi = 0; mi < 4; mi++) {
        #pragma unroll
        for (int ni = 0; ni < 4; ni++) {
            OutT* p0 = C + (size_t)(bm + warp_m + mi * 16 + er) * Ntot + bn + warp_n + ni * 8 + ec;
            if constexpr (sizeof(OutT) == 2) {
                *(__half2*)p0 = __floats2half2_rn(acc[mi][ni][0], acc[mi][ni][1]);
                *(__half2*)(p0 + (size_t)8 * Ntot) = __floats2half2_rn(acc[mi][ni][2], acc[mi][ni][3]);
            } else {
                *(float2*)p0                      = make_float2(acc[mi][ni][0], acc[mi][ni][1]);
                *(float2*)(p0 + (size_t)8 * Ntot) = make_float2(acc[mi][ni][2], acc[mi][ni][3]);
            }
        }
    }
}

// ---------------------------------------------------------------------------
// fused prep: x->fp16 (blocks 0..8191), w_qkv^T (next 768), w_out^T (next 256)
// ---------------------------------------------------------------------------
__global__ __launch_bounds__(256) void prep_kernel(
    const float* __restrict__ x,     __half* __restrict__ xh,
    const float* __restrict__ wq,    __half* __restrict__ wqh,
    const float* __restrict__ wo,    __half* __restrict__ woh)
{
    const int bid = blockIdx.x;
    const int tid = threadIdx.x;
    if (bid < 8192) {
        const size_t i = ((size_t)bid * 256 + tid) * 4;
        float4 v = *(const float4*)(x + i);
        *(__half2*)(xh + i)     = __floats2half2_rn(v.x, v.y);
        *(__half2*)(xh + i + 2) = __floats2half2_rn(v.z, v.w);
        return;
    }
    __shared__ float t[32][33];
    const float* w;  __half* wT;  int N, bx, by;
    if (bid < 8192 + 768) {          // w_qkv: [512,1536]
        w = wq; wT = wqh; N = 3 * CDIM;
        const int r = bid - 8192;
        bx = r % 48; by = r / 48;
    } else {                          // w_out: [512,512]
        w = wo; wT = woh; N = CDIM;
        const int r = bid - 8960;
        bx = r % 16; by = r / 16;
    }
    const int k0 = by * 32;
    const int n0 = bx * 32;
    const int tx = tid & 31, ty = tid >> 5;
    #pragma unroll
    for (int i = ty; i < 32; i += 8)
        t[i][tx] = w[(size_t)(k0 + i) * N + n0 + tx];
    __syncthreads();
    #pragma unroll
    for (int i = ty; i < 32; i += 8)
        wT[(size_t)(n0 + i) * CDIM + k0 + tx] = __float2half(t[tx][i]);
}

// ---------------------------------------------------------------------------
// Warp-per-token windowed attention over fp16 qkv; fp16 output
// ---------------------------------------------------------------------------
__global__ __launch_bounds__(256) void attn_kernel(const float* __restrict__ x,
                                                   const float* __restrict__ w_width,
                                                   const float* __restrict__ b_width,
                                                   __half* __restrict__ att)
{
    const int gwarp = (blockIdx.x * blockDim.x + threadIdx.x) >> 5;
    const int lane = threadIdx.x & 31;
    if (gwarp >= NTOK) return;

    const int b = gwarp >> 13;
    const int l = gwarp & (LSEQ - 1);

    const __half* qkv = g_qkvh;

    float q[16];
    {
        const uint4* q4 = (const uint4*)(qkv + (size_t)gwarp * 3 * CDIM);
        #pragma unroll
        for (int i = 0; i < 2; i++) unpack8(q4[lane + 32 * i], q + 8 * i);
    }

    const float4* x4 = (const float4*)(x + (size_t)gwarp * CDIM);
    const float4* w4 = (const float4*)w_width;
    float wsum = 0.f;
    #pragma unroll
    for (int i = 0; i < 4; i++) {
        const float4 xv = x4[lane + 32 * i];
        const float4 wv = w4[lane + 32 * i];
        wsum += xv.x * wv.x + xv.y * wv.y + xv.z * wv.z + xv.w * wv.w;
    }
    #pragma unroll
    for (int o = 16; o > 0; o >>= 1) wsum += __shfl_xor_sync(0xffffffffu, wsum, o);
    const float width = 1.f / (1.f + expf(-(wsum + b_width[0]))) * (float)(KWIN - 1) + 1.f;

    float sc[KWIN];
    #pragma unroll
    for (int j = 0; j < KWIN; j++) {
        const int row = l + j - HALFK;
        float s = 0.f;
        if (row >= 0 && row < LSEQ) {
            const uint4* k4 = (const uint4*)(qkv + ((size_t)(b * LSEQ + row) * 3 + 1) * CDIM);
            #pragma unroll
            for (int i = 0; i < 2; i++) {
                float kf[8];
                unpack8(k4[lane + 32 * i], kf);
                #pragma unroll
                for (int t = 0; t < 8; t++) s += q[8 * i + t] * kf[t];
            }
        }
        #pragma unroll
        for (int o = 16; o > 0; o >>= 1) s += __shfl_xor_sync(0xffffffffu, s, o);
        sc[j] = s;
    }

    const float scale = 0.044194173824159216f;
    float mx = -1e30f;
    #pragma unroll
    for (int j = 0; j < KWIN; j++) {
        const float rel = fabsf((float)j - (float)HALFK);
        const float m = 1.f / (1.f + expf(-(width - rel) * 5.f));
        sc[j] = sc[j] * scale - (1.f - m) * 10000.f;
        mx = fmaxf(mx, sc[j]);
    }
    float denom = 0.f;
    #pragma unroll
    for (int j = 0; j < KWIN; j++) {
        sc[j] = expf(sc[j] - mx);
        denom += sc[j];
    }
    const float inv = 1.f / denom;

    float acc[16];
    {
        const uint4* vs = (const uint4*)(qkv + ((size_t)gwarp * 3 + 2) * CDIM);
        #pragma unroll
        for (int i = 0; i < 2; i++) unpack8(vs[lane + 32 * i], acc + 8 * i);
    }

    #pragma unroll
    for (int j = 0; j < KWIN; j++) {
        const int row = l + j - HALFK;
        if (row < 0 || row >= LSEQ) continue;
        const float a = sc[j] * inv;
        const uint4* v4 = (const uint4*)(qkv + ((size_t)(b * LSEQ + row) * 3 + 2) * CDIM);
        #pragma unroll
        for (int i = 0; i < 2; i++) {
            float vf[8];
            unpack8(v4[lane + 32 * i], vf);
            #pragma unroll
            for (int t = 0; t < 8; t++) acc[8 * i + t] += a * vf[t];
        }
    }

    uint4* arow = (uint4*)(att + (size_t)gwarp * CDIM);
    #pragma unroll
    for (int i = 0; i < 2; i++) {
        uint4 uh;
        __half2* hh = (__half2*)&uh;
        #pragma unroll
        for (int t = 0; t < 4; t++)
            hh[t] = __floats2half2_rn(acc[8 * i + 2 * t], acc[8 * i + 2 * t + 1]);
        arow[lane + 32 * i] = uh;
    }
}

// ---------------------------------------------------------------------------
extern "C" void kernel_launch(void* const* d_in, const int* in_sizes, int n_in,
                              void* d_out, int out_size)
{
    const float* x       = (const float*)d_in[0];
    const float* w_qkv   = (const float*)d_in[1];
    const float* w_width = (const float*)d_in[2];
    const float* b_width = (const float*)d_in[3];
    const float* w_out   = (const float*)d_in[4];
    float* out = (float*)d_out;

    __half* qkvh; cudaGetSymbolAddress((void**)&qkvh, g_qkvh);
    __half* xh;   cudaGetSymbolAddress((void**)&xh,   g_xh);
    __half* ah;   cudaGetSymbolAddress((void**)&ah,   g_ah);
    __half* wqh;  cudaGetSymbolAddress((void**)&wqh,  g_wqh);
    __half* woh;  cudaGetSymbolAddress((void**)&woh,  g_woh);

    cudaFuncSetAttribute(gemm_mma<__half>, cudaFuncAttributeMaxDynamicSharedMemorySize, GEMM_SMEM);
    cudaFuncSetAttribute(gemm_mma<float>,  cudaFuncAttributeMaxDynamicSharedMemorySize, GEMM_SMEM);

    // 0) fused prep: x->fp16 + both weight transposes
    prep_kernel<<<8192 + 768 + 256, 256>>>(x, xh, w_qkv, wqh, w_out, woh);

    // 1) qkv = x @ w_qkv   (fp16 in, fp16 out)
    {
        dim3 grid(3 * CDIM / 128, NTOK / 128);
        gemm_mma<__half><<<grid, 256, GEMM_SMEM>>>(xh, wqh, qkvh, 3 * CDIM);
    }

    // 2) fused windowed attention (fp16 qkv) -> att (fp16)
    attn_kernel<<<NTOK / 8, 256>>>(x, w_width, b_width, ah);

    // 3) out = att @ w_out  (fp16 in, fp32 out)
    {
        dim3 grid(CDIM / 128, NTOK / 128);
        gemm_mma<float><<<grid, 256, GEMM_SMEM>>>(ah, woh, out, CDIM);
    }
}

// round 13
// speedup vs baseline: 1.2673x; 1.0771x over previous
#include <cuda_runtime.h>
#include <cuda_fp16.h>
#include <cstdint>

// Problem constants
#define BDIM 2
#define LSEQ 8192
#define CDIM 512
#define KWIN 17
#define HALFK 8
#define NTOK (BDIM * LSEQ)      // 16384

// ---------------------------------------------------------------------------
// Scratch (__device__ globals; no cudaMalloc allowed)
// ---------------------------------------------------------------------------
__device__ __half  g_qkvh[(size_t)NTOK * 3 * CDIM];    // 48 MB fp16 qkv
__device__ __half  g_xh[(size_t)NTOK * CDIM];          // x   -> fp16
__device__ __half  g_ah[(size_t)NTOK * CDIM];          // att -> fp16
__device__ __half  g_wqh[(size_t)3 * CDIM * CDIM];     // w_qkv^T fp16
__device__ __half  g_woh[(size_t)CDIM * CDIM];         // w_out^T fp16

// ---------------------------------------------------------------------------
// helpers
// ---------------------------------------------------------------------------
__device__ __forceinline__ uint32_t smem_u32(const void* p) {
    uint32_t a;
    asm("{ .reg .u64 t; cvta.to.shared.u64 t, %1; cvt.u32.u64 %0, t; }" : "=r"(a) : "l"(p));
    return a;
}
__device__ __forceinline__ void cp16(uint32_t dst, const void* src) {
    asm volatile("cp.async.cg.shared.global [%0], [%1], 16;" :: "r"(dst), "l"(src));
}
__device__ __forceinline__ void ldsm_x4(uint32_t* r, uint32_t addr) {
    asm volatile("ldmatrix.sync.aligned.m8n8.x4.shared.b16 {%0,%1,%2,%3}, [%4];"
                 : "=r"(r[0]), "=r"(r[1]), "=r"(r[2]), "=r"(r[3]) : "r"(addr));
}
__device__ __forceinline__ void mma_f16(float* c, const uint32_t* a, const uint32_t* b) {
    asm volatile(
        "mma.sync.aligned.m16n8k16.row.col.f32.f16.f16.f32 "
        "{%0,%1,%2,%3}, {%4,%5,%6,%7}, {%8,%9}, {%0,%1,%2,%3};"
        : "+f"(c[0]), "+f"(c[1]), "+f"(c[2]), "+f"(c[3])
        : "r"(a[0]), "r"(a[1]), "r"(a[2]), "r"(a[3]), "r"(b[0]), "r"(b[1]));
}
#define CPWAIT(N) asm volatile("cp.async.wait_group %0;" :: "n"(N))

__device__ __forceinline__ void unpack8(uint4 u, float* f) {
    const __half2* h = (const __half2*)&u;
    #pragma unroll
    for (int t = 0; t < 4; t++) {
        float2 v = __half22float2(h[t]);
        f[2 * t] = v.x;
        f[2 * t + 1] = v.y;
    }
}

// ---------------------------------------------------------------------------
// Plain fp16 GEMM:  C = A @ B^T  (fp32 accum, OutT store)
// Block 128x128, 8 warps (2x4), warp 64x32.  BK=64 stages, 3 buffers,
// ONE __syncthreads per stage, cp.async for s+2 issued AFTER compute.
// B fragments loaded with ldmatrix.x4 (two n-tiles per instr).  2 CTAs/SM.
// PITCH=144 -> conflict-free ldmatrix.
// ---------------------------------------------------------------------------
#define GK       512
#define BK       64
#define NSTG     (GK / BK)          // 8
#define NBUF     3
#define PITCH    144
#define A_SZ     (128 * PITCH)      // 18432
#define STG_SZ   (2 * A_SZ)         // A | B = 36864
#define GEMM_SMEM (NBUF * STG_SZ)   // 110592

template <typename OutT>
__global__ __launch_bounds__(256, 2) void gemm_mma(
    const __half* __restrict__ A, const __half* __restrict__ B,
    OutT* __restrict__ C, int Ntot)
{
    extern __shared__ char smem[];
    const uint32_t sb = smem_u32(smem);
    const int tid  = threadIdx.x;
    const int wid  = tid >> 5;
    const int lane = tid & 31;
    const int bm = blockIdx.y * 128;
    const int bn = blockIdx.x * 128;
    const int warp_m = (wid >> 2) * 64;
    const int warp_n = (wid & 3) * 32;

    auto load_stage = [&](int s, int b) {
        const int k0 = s * BK;
        const uint32_t buf = sb + (uint32_t)b * STG_SZ;
        #pragma unroll
        for (int r = 0; r < 4; r++) {
            const int i   = tid + 256 * r;
            const int row = i >> 3;
            const int c16 = (i & 7) * 16;
            const uint32_t off = (uint32_t)(row * PITCH + c16);
            cp16(buf + off,        A + (size_t)(bm + row) * GK + k0 + (c16 >> 1));
            cp16(buf + A_SZ + off, B + (size_t)(bn + row) * GK + k0 + (c16 >> 1));
        }
        asm volatile("cp.async.commit_group;" ::: "memory");
    };

    float acc[4][4][4];
    #pragma unroll
    for (int mi = 0; mi < 4; mi++)
        #pragma unroll
        for (int ni = 0; ni < 4; ni++)
            #pragma unroll
            for (int f = 0; f < 4; f++) acc[mi][ni][f] = 0.f;

    const uint32_t aLane = (uint32_t)((warp_m + (lane & 15)) * PITCH + ((lane >> 4) & 1) * 16);
    // x4 B address: lanes 0-7 -> n0-7/khalf0, 8-15 -> n0-7/khalf1,
    //               16-23 -> n8-15/khalf0, 24-31 -> n8-15/khalf1
    const uint32_t bLane4 = (uint32_t)((warp_n + ((lane >> 4) << 3) + (lane & 7)) * PITCH
                                       + ((lane >> 3) & 1) * 16);

    load_stage(0, 0);
    load_stage(1, 1);

    for (int s = 0; s < NSTG; s++) {
        const int b = s % NBUF;
        if (s + 1 < NSTG) CPWAIT(1);
        else              CPWAIT(0);
        __syncthreads();

        const uint32_t buf = sb + (uint32_t)b * STG_SZ;
        #pragma unroll
        for (int kk = 0; kk < 4; kk++) {
            const uint32_t ko = (uint32_t)(kk * 32);
            uint32_t ah[4][4], bh[4][2];
            #pragma unroll
            for (int mi = 0; mi < 4; mi++)
                ldsm_x4(ah[mi], buf + aLane + (uint32_t)(mi * 16 * PITCH) + ko);
            ldsm_x4(&bh[0][0], buf + A_SZ + bLane4 + ko);                           // ni 0,1
            ldsm_x4(&bh[2][0], buf + A_SZ + bLane4 + (uint32_t)(16 * PITCH) + ko);  // ni 2,3
            #pragma unroll
            for (int mi = 0; mi < 4; mi++)
                #pragma unroll
                for (int ni = 0; ni < 4; ni++)
                    mma_f16(acc[mi][ni], ah[mi], bh[ni]);
        }

        if (s + 2 < NSTG) load_stage(s + 2, (s + 2) % NBUF);
    }

    const int er = lane >> 2;
    const int ec = (lane & 3) * 2;
    #pragma unroll
    for (int mi = 0; mi < 4; mi++) {
        #pragma unroll
        for (int ni = 0; ni < 4; ni++) {
            OutT* p0 = C + (size_t)(bm + warp_m + mi * 16 + er) * Ntot + bn + warp_n + ni * 8 + ec;
            if constexpr (sizeof(OutT) == 2) {
                *(__half2*)p0 = __floats2half2_rn(acc[mi][ni][0], acc[mi][ni][1]);
                *(__half2*)(p0 + (size_t)8 * Ntot) = __floats2half2_rn(acc[mi][ni][2], acc[mi][ni][3]);
            } else {
                *(float2*)p0                      = make_float2(acc[mi][ni][0], acc[mi][ni][1]);
                *(float2*)(p0 + (size_t)8 * Ntot) = make_float2(acc[mi][ni][2], acc[mi][ni][3]);
            }
        }
    }
}

// ---------------------------------------------------------------------------
// fused prep: x->fp16 (blocks 0..8191), w_qkv^T (next 768), w_out^T (next 256)
// ---------------------------------------------------------------------------
__global__ __launch_bounds__(256) void prep_kernel(
    const float* __restrict__ x,     __half* __restrict__ xh,
    const float* __restrict__ wq,    __half* __restrict__ wqh,
    const float* __restrict__ wo,    __half* __restrict__ woh)
{
    const int bid = blockIdx.x;
    const int tid = threadIdx.x;
    if (bid < 8192) {
        const size_t i = ((size_t)bid * 256 + tid) * 4;
        float4 v = *(const float4*)(x + i);
        *(__half2*)(xh + i)     = __floats2half2_rn(v.x, v.y);
        *(__half2*)(xh + i + 2) = __floats2half2_rn(v.z, v.w);
        return;
    }
    __shared__ float t[32][33];
    const float* w;  __half* wT;  int N, bx, by;
    if (bid < 8192 + 768) {
        w = wq; wT = wqh; N = 3 * CDIM;
        const int r = bid - 8192;
        bx = r % 48; by = r / 48;
    } else {
        w = wo; wT = woh; N = CDIM;
        const int r = bid - 8960;
        bx = r % 16; by = r / 16;
    }
    const int k0 = by * 32;
    const int n0 = bx * 32;
    const int tx = tid & 31, ty = tid >> 5;
    #pragma unroll
    for (int i = ty; i < 32; i += 8)
        t[i][tx] = w[(size_t)(k0 + i) * N + n0 + tx];
    __syncthreads();
    #pragma unroll
    for (int i = ty; i < 32; i += 8)
        wT[(size_t)(n0 + i) * CDIM + k0 + tx] = __float2half(t[tx][i]);
}

// ---------------------------------------------------------------------------
// Windowed attention, TWO tokens per warp (adjacent windows share 16 of 17
// k/v rows -> each row loaded once for both tokens).  fp16 qkv, fp16 out.
// ---------------------------------------------------------------------------
__global__ __launch_bounds__(256) void attn_kernel(const float* __restrict__ x,
                                                   const float* __restrict__ w_width,
                                                   const float* __restrict__ b_width,
                                                   __half* __restrict__ att)
{
    const int gw = (blockIdx.x * blockDim.x + threadIdx.x) >> 5;   // pair id
    const int lane = threadIdx.x & 31;
    if (gw >= NTOK / 2) return;

    const int b  = gw >> 12;               // 4096 pairs per batch
    const int l0 = (gw & 4095) << 1;
    const size_t tok0 = (size_t)b * LSEQ + l0;

    const __half* qkv = g_qkvh;

    // q for both tokens
    float q0[16], q1[16];
    {
        const uint4* qa = (const uint4*)(qkv + tok0 * 3 * CDIM);
        const uint4* qb = (const uint4*)(qkv + (tok0 + 1) * 3 * CDIM);
        #pragma unroll
        for (int i = 0; i < 2; i++) {
            unpack8(qa[lane + 32 * i], q0 + 8 * i);
            unpack8(qb[lane + 32 * i], q1 + 8 * i);
        }
    }

    // widths for both tokens
    const float4* w4 = (const float4*)w_width;
    float ws0 = 0.f, ws1 = 0.f;
    {
        const float4* xa = (const float4*)(x + tok0 * CDIM);
        const float4* xb = (const float4*)(x + (tok0 + 1) * CDIM);
        #pragma unroll
        for (int i = 0; i < 4; i++) {
            const float4 wv = w4[lane + 32 * i];
            const float4 va = xa[lane + 32 * i];
            const float4 vb = xb[lane + 32 * i];
            ws0 += va.x * wv.x + va.y * wv.y + va.z * wv.z + va.w * wv.w;
            ws1 += vb.x * wv.x + vb.y * wv.y + vb.z * wv.z + vb.w * wv.w;
        }
        #pragma unroll
        for (int o = 16; o > 0; o >>= 1) {
            ws0 += __shfl_xor_sync(0xffffffffu, ws0, o);
            ws1 += __shfl_xor_sync(0xffffffffu, ws1, o);
        }
    }
    const float bw = b_width[0];
    const float width0 = 1.f / (1.f + expf(-(ws0 + bw))) * (float)(KWIN - 1) + 1.f;
    const float width1 = 1.f / (1.f + expf(-(ws1 + bw))) * (float)(KWIN - 1) + 1.f;

    // scores: 18 shared rows (l0-8 .. l0+9)
    float sc0[KWIN], sc1[KWIN];
    #pragma unroll
    for (int rr = 0; rr < KWIN + 1; rr++) {
        const int row = l0 - HALFK + rr;
        float s0 = 0.f, s1 = 0.f;
        if (row >= 0 && row < LSEQ) {
            const uint4* k4 = (const uint4*)(qkv + ((size_t)(b * LSEQ + row) * 3 + 1) * CDIM);
            #pragma unroll
            for (int i = 0; i < 2; i++) {
                float kf[8];
                unpack8(k4[lane + 32 * i], kf);
                #pragma unroll
                for (int t = 0; t < 8; t++) {
                    s0 += q0[8 * i + t] * kf[t];
                    s1 += q1[8 * i + t] * kf[t];
                }
            }
        }
        #pragma unroll
        for (int o = 16; o > 0; o >>= 1) {
            s0 += __shfl_xor_sync(0xffffffffu, s0, o);
            s1 += __shfl_xor_sync(0xffffffffu, s1, o);
        }
        if (rr < KWIN) sc0[rr] = s0;
        if (rr > 0)    sc1[rr - 1] = s1;
    }

    // mask + softmax (both tokens)
    const float scale = 0.044194173824159216f;
    float mx0 = -1e30f, mx1 = -1e30f;
    #pragma unroll
    for (int j = 0; j < KWIN; j++) {
        const float rel = fabsf((float)j - (float)HALFK);
        const float m0 = 1.f / (1.f + expf(-(width0 - rel) * 5.f));
        const float m1 = 1.f / (1.f + expf(-(width1 - rel) * 5.f));
        sc0[j] = sc0[j] * scale - (1.f - m0) * 10000.f;
        sc1[j] = sc1[j] * scale - (1.f - m1) * 10000.f;
        mx0 = fmaxf(mx0, sc0[j]);
        mx1 = fmaxf(mx1, sc1[j]);
    }
    float d0 = 0.f, d1 = 0.f;
    #pragma unroll
    for (int j = 0; j < KWIN; j++) {
        sc0[j] = expf(sc0[j] - mx0);  d0 += sc0[j];
        sc1[j] = expf(sc1[j] - mx1);  d1 += sc1[j];
    }
    const float inv0 = 1.f / d0, inv1 = 1.f / d1;

    // out = attn @ v_win + v_self (both tokens), 18 shared v rows
    float acc0[16], acc1[16];
    {
        const uint4* va = (const uint4*)(qkv + (tok0 * 3 + 2) * CDIM);
        const uint4* vb = (const uint4*)(qkv + ((tok0 + 1) * 3 + 2) * CDIM);
        #pragma unroll
        for (int i = 0; i < 2; i++) {
            unpack8(va[lane + 32 * i], acc0 + 8 * i);
            unpack8(vb[lane + 32 * i], acc1 + 8 * i);
        }
    }
    #pragma unroll
    for (int rr = 0; rr < KWIN + 1; rr++) {
        const int row = l0 - HALFK + rr;
        if (row < 0 || row >= LSEQ) continue;
        const float a0 = (rr < KWIN) ? sc0[rr] * inv0 : 0.f;
        const float a1 = (rr > 0)    ? sc1[rr - 1] * inv1 : 0.f;
        const uint4* v4 = (const uint4*)(qkv + ((size_t)(b * LSEQ + row) * 3 + 2) * CDIM);
        #pragma unroll
        for (int i = 0; i < 2; i++) {
            float vf[8];
            unpack8(v4[lane + 32 * i], vf);
            #pragma unroll
            for (int t = 0; t < 8; t++) {
                acc0[8 * i + t] += a0 * vf[t];
                acc1[8 * i + t] += a1 * vf[t];
            }
        }
    }

    uint4* r0 = (uint4*)(att + tok0 * CDIM);
    uint4* r1 = (uint4*)(att + (tok0 + 1) * CDIM);
    #pragma unroll
    for (int i = 0; i < 2; i++) {
        uint4 u0, u1;
        __half2* h0 = (__half2*)&u0;
        __half2* h1 = (__half2*)&u1;
        #pragma unroll
        for (int t = 0; t < 4; t++) {
            h0[t] = __floats2half2_rn(acc0[8 * i + 2 * t], acc0[8 * i + 2 * t + 1]);
            h1[t] = __floats2half2_rn(acc1[8 * i + 2 * t], acc1[8 * i + 2 * t + 1]);
        }
        r0[lane + 32 * i] = u0;
        r1[lane + 32 * i] = u1;
    }
}

// ---------------------------------------------------------------------------
extern "C" void kernel_launch(void* const* d_in, const int* in_sizes, int n_in,
                              void* d_out, int out_size)
{
    const float* x       = (const float*)d_in[0];
    const float* w_qkv   = (const float*)d_in[1];
    const float* w_width = (const float*)d_in[2];
    const float* b_width = (const float*)d_in[3];
    const float* w_out   = (const float*)d_in[4];
    float* out = (float*)d_out;

    __half* qkvh; cudaGetSymbolAddress((void**)&qkvh, g_qkvh);
    __half* xh;   cudaGetSymbolAddress((void**)&xh,   g_xh);
    __half* ah;   cudaGetSymbolAddress((void**)&ah,   g_ah);
    __half* wqh;  cudaGetSymbolAddress((void**)&wqh,  g_wqh);
    __half* woh;  cudaGetSymbolAddress((void**)&woh,  g_woh);

    cudaFuncSetAttribute(gemm_mma<__half>, cudaFuncAttributeMaxDynamicSharedMemorySize, GEMM_SMEM);
    cudaFuncSetAttribute(gemm_mma<float>,  cudaFuncAttributeMaxDynamicSharedMemorySize, GEMM_SMEM);

    // 0) fused prep: x->fp16 + both weight transposes
    prep_kernel<<<8192 + 768 + 256, 256>>>(x, xh, w_qkv, wqh, w_out, woh);

    // 1) qkv = x @ w_qkv   (fp16 in, fp16 out)
    {
        dim3 grid(3 * CDIM / 128, NTOK / 128);
        gemm_mma<__half><<<grid, 256, GEMM_SMEM>>>(xh, wqh, qkvh, 3 * CDIM);
    }

    // 2) fused windowed attention (2 tokens/warp) -> att (fp16)
    attn_kernel<<<NTOK / 16, 256>>>(x, w_width, b_width, ah);

    // 3) out = att @ w_out  (fp16 in, fp32 out)
    {
        dim3 grid(CDIM / 128, NTOK / 128);
        gemm_mma<float><<<grid, 256, GEMM_SMEM>>>(ah, woh, out, CDIM);
    }
}

// round 14
// speedup vs baseline: 1.4232x; 1.1230x over previous
#include <cuda_runtime.h>
#include <cuda_fp16.h>
#include <cstdint>

// Problem constants
#define BDIM 2
#define LSEQ 8192
#define CDIM 512
#define KWIN 17
#define HALFK 8
#define NTOK (BDIM * LSEQ)      // 16384

// ---------------------------------------------------------------------------
// Scratch (__device__ globals; no cudaMalloc allowed)
// ---------------------------------------------------------------------------
__device__ __half  g_qkvh[(size_t)NTOK * 3 * CDIM];    // 48 MB fp16 qkv
__device__ __half  g_xh[(size_t)NTOK * CDIM];          // x   -> fp16
__device__ __half  g_ah[(size_t)NTOK * CDIM];          // att -> fp16
__device__ __half  g_wqh[(size_t)3 * CDIM * CDIM];     // w_qkv^T fp16
__device__ __half  g_woh[(size_t)CDIM * CDIM];         // w_out^T fp16

// ---------------------------------------------------------------------------
// helpers
// ---------------------------------------------------------------------------
__device__ __forceinline__ uint32_t smem_u32(const void* p) {
    uint32_t a;
    asm("{ .reg .u64 t; cvta.to.shared.u64 t, %1; cvt.u32.u64 %0, t; }" : "=r"(a) : "l"(p));
    return a;
}
__device__ __forceinline__ void cp16(uint32_t dst, const void* src) {
    asm volatile("cp.async.cg.shared.global [%0], [%1], 16;" :: "r"(dst), "l"(src));
}
__device__ __forceinline__ void ldsm_x4(uint32_t* r, uint32_t addr) {
    asm volatile("ldmatrix.sync.aligned.m8n8.x4.shared.b16 {%0,%1,%2,%3}, [%4];"
                 : "=r"(r[0]), "=r"(r[1]), "=r"(r[2]), "=r"(r[3]) : "r"(addr));
}
__device__ __forceinline__ void ldsm_x2(uint32_t* r, uint32_t addr) {
    asm volatile("ldmatrix.sync.aligned.m8n8.x2.shared.b16 {%0,%1}, [%2];"
                 : "=r"(r[0]), "=r"(r[1]) : "r"(addr));
}
__device__ __forceinline__ void ldsm_x4_t(uint32_t* r, uint32_t addr) {
    asm volatile("ldmatrix.sync.aligned.m8n8.x4.trans.shared.b16 {%0,%1,%2,%3}, [%4];"
                 : "=r"(r[0]), "=r"(r[1]), "=r"(r[2]), "=r"(r[3]) : "r"(addr));
}
__device__ __forceinline__ void mma_f16(float* c, const uint32_t* a, const uint32_t* b) {
    asm volatile(
        "mma.sync.aligned.m16n8k16.row.col.f32.f16.f16.f32 "
        "{%0,%1,%2,%3}, {%4,%5,%6,%7}, {%8,%9}, {%0,%1,%2,%3};"
        : "+f"(c[0]), "+f"(c[1]), "+f"(c[2]), "+f"(c[3])
        : "r"(a[0]), "r"(a[1]), "r"(a[2]), "r"(a[3]), "r"(b[0]), "r"(b[1]));
}
#define CPWAIT(N) asm volatile("cp.async.wait_group %0;" :: "n"(N))
#define CPCOMMIT() asm volatile("cp.async.commit_group;" ::: "memory")

__device__ __forceinline__ void sts_zero16(uint32_t dst) {
    asm volatile("st.shared.v4.b32 [%0], {%1,%1,%1,%1};" :: "r"(dst), "r"(0) : "memory");
}
__device__ __forceinline__ void cp16z(uint32_t dst, const __half* src, bool valid) {
    if (valid) cp16(dst, src);
    else       sts_zero16(dst);
}

// ---------------------------------------------------------------------------
// Plain fp16 GEMM:  C = A @ B^T  (fp32 accum, OutT store)   [R13 winner]
// ---------------------------------------------------------------------------
#define GK       512
#define BK       64
#define NSTG     (GK / BK)          // 8
#define NBUF     3
#define PITCH    144
#define A_SZ     (128 * PITCH)      // 18432
#define STG_SZ   (2 * A_SZ)         // 36864
#define GEMM_SMEM (NBUF * STG_SZ)   // 110592

template <typename OutT>
__global__ __launch_bounds__(256, 2) void gemm_mma(
    const __half* __restrict__ A, const __half* __restrict__ B,
    OutT* __restrict__ C, int Ntot)
{
    extern __shared__ char smem[];
    const uint32_t sb = smem_u32(smem);
    const int tid  = threadIdx.x;
    const int wid  = tid >> 5;
    const int lane = tid & 31;
    const int bm = blockIdx.y * 128;
    const int bn = blockIdx.x * 128;
    const int warp_m = (wid >> 2) * 64;
    const int warp_n = (wid & 3) * 32;

    auto load_stage = [&](int s, int b) {
        const int k0 = s * BK;
        const uint32_t buf = sb + (uint32_t)b * STG_SZ;
        #pragma unroll
        for (int r = 0; r < 4; r++) {
            const int i   = tid + 256 * r;
            const int row = i >> 3;
            const int c16 = (i & 7) * 16;
            const uint32_t off = (uint32_t)(row * PITCH + c16);
            cp16(buf + off,        A + (size_t)(bm + row) * GK + k0 + (c16 >> 1));
            cp16(buf + A_SZ + off, B + (size_t)(bn + row) * GK + k0 + (c16 >> 1));
        }
        CPCOMMIT();
    };

    float acc[4][4][4];
    #pragma unroll
    for (int mi = 0; mi < 4; mi++)
        #pragma unroll
        for (int ni = 0; ni < 4; ni++)
            #pragma unroll
            for (int f = 0; f < 4; f++) acc[mi][ni][f] = 0.f;

    const uint32_t aLane = (uint32_t)((warp_m + (lane & 15)) * PITCH + ((lane >> 4) & 1) * 16);
    const uint32_t bLane4 = (uint32_t)((warp_n + ((lane >> 4) << 3) + (lane & 7)) * PITCH
                                       + ((lane >> 3) & 1) * 16);

    load_stage(0, 0);
    load_stage(1, 1);

    for (int s = 0; s < NSTG; s++) {
        const int b = s % NBUF;
        if (s + 1 < NSTG) CPWAIT(1);
        else              CPWAIT(0);
        __syncthreads();

        const uint32_t buf = sb + (uint32_t)b * STG_SZ;
        #pragma unroll
        for (int kk = 0; kk < 4; kk++) {
            const uint32_t ko = (uint32_t)(kk * 32);
            uint32_t ah[4][4], bh[4][2];
            #pragma unroll
            for (int mi = 0; mi < 4; mi++)
                ldsm_x4(ah[mi], buf + aLane + (uint32_t)(mi * 16 * PITCH) + ko);
            ldsm_x4(&bh[0][0], buf + A_SZ + bLane4 + ko);
            ldsm_x4(&bh[2][0], buf + A_SZ + bLane4 + (uint32_t)(16 * PITCH) + ko);
            #pragma unroll
            for (int mi = 0; mi < 4; mi++)
                #pragma unroll
                for (int ni = 0; ni < 4; ni++)
                    mma_f16(acc[mi][ni], ah[mi], bh[ni]);
        }

        if (s + 2 < NSTG) load_stage(s + 2, (s + 2) % NBUF);
    }

    const int er = lane >> 2;
    const int ec = (lane & 3) * 2;
    #pragma unroll
    for (int mi = 0; mi < 4; mi++) {
        #pragma unroll
        for (int ni = 0; ni < 4; ni++) {
            OutT* p0 = C + (size_t)(bm + warp_m + mi * 16 + er) * Ntot + bn + warp_n + ni * 8 + ec;
            if constexpr (sizeof(OutT) == 2) {
                *(__half2*)p0 = __floats2half2_rn(acc[mi][ni][0], acc[mi][ni][1]);
                *(__half2*)(p0 + (size_t)8 * Ntot) = __floats2half2_rn(acc[mi][ni][2], acc[mi][ni][3]);
            } else {
                *(float2*)p0                      = make_float2(acc[mi][ni][0], acc[mi][ni][1]);
                *(float2*)(p0 + (size_t)8 * Ntot) = make_float2(acc[mi][ni][2], acc[mi][ni][3]);
            }
        }
    }
}

// ---------------------------------------------------------------------------
// fused prep: x->fp16 (blocks 0..8191), w_qkv^T (next 768), w_out^T (next 256)
// ---------------------------------------------------------------------------
__global__ __launch_bounds__(256) void prep_kernel(
    const float* __restrict__ x,     __half* __restrict__ xh,
    const float* __restrict__ wq,    __half* __restrict__ wqh,
    const float* __restrict__ wo,    __half* __restrict__ woh)
{
    const int bid = blockIdx.x;
    const int tid = threadIdx.x;
    if (bid < 8192) {
        const size_t i = ((size_t)bid * 256 + tid) * 4;
        float4 v = *(const float4*)(x + i);
        *(__half2*)(xh + i)     = __floats2half2_rn(v.x, v.y);
        *(__half2*)(xh + i + 2) = __floats2half2_rn(v.z, v.w);
        return;
    }
    __shared__ float t[32][33];
    const float* w;  __half* wT;  int N, bx, by;
    if (bid < 8192 + 768) {
        w = wq; wT = wqh; N = 3 * CDIM;
        const int r = bid - 8192;
        bx = r % 48; by = r / 48;
    } else {
        w = wo; wT = woh; N = CDIM;
        const int r = bid - 8960;
        bx = r % 16; by = r / 16;
    }
    const int k0 = by * 32;
    const int n0 = bx * 32;
    const int tx = tid & 31, ty = tid >> 5;
    #pragma unroll
    for (int i = ty; i < 32; i += 8)
        t[i][tx] = w[(size_t)(k0 + i) * N + n0 + tx];
    __syncthreads();
    #pragma unroll
    for (int i = ty; i < 32; i += 8)
        wT[(size_t)(n0 + i) * CDIM + k0 + tx] = __float2half(t[tx][i]);
}

// ---------------------------------------------------------------------------
// MMA attention: 128 threads / 32 tokens per block.
// Phase 1: S[32x48] = Q @ K_win^T via HMMA (8 k-chunks of 64, OOB K rows = 0)
// Phase 2: per-token soft mask + softmax on the 48-col band (reference
//          semantics: OOB positions keep s=0 and stay in the denominator)
// Phase 3: att = W[32x48] @ V[48x512] via HMMA (8 n-chunks, V OOB = 0,
//          ldmatrix.trans for V), + exact v_self from the resident V tile.
// ---------------------------------------------------------------------------
#define ATB   32
#define AWIN  48
#define APIT  72          // halves per row (144 B)

__global__ __launch_bounds__(128) void attn_kernel(const float* __restrict__ x,
                                                   const float* __restrict__ w_width,
                                                   const float* __restrict__ b_width,
                                                   __half* __restrict__ att)
{
    __shared__ __align__(128) __half shQ[ATB * APIT];    // 4608 B
    __shared__ __align__(128) __half shK[AWIN * APIT];   // 6912 B
    __shared__ __align__(128) float  shS[ATB * 48];      // 6144 B
    __shared__ __align__(128) __half shW[ATB * APIT];    // 4608 B
    __shared__ __align__(128) __half shV[AWIN * APIT];   // 6912 B
    __shared__ float shWidth[ATB];

    const int tid  = threadIdx.x;
    const int wid  = tid >> 5;
    const int lane = tid & 31;
    const int tok0 = blockIdx.x * ATB;          // global token base
    const int l0   = tok0 & (LSEQ - 1);
    const int g0   = l0 - HALFK;                // first window l-index
    const size_t gbase = (size_t)(tok0 >> 13) * LSEQ;

    const __half* qkv = g_qkvh;
    const uint32_t qb = smem_u32(shQ);
    const uint32_t kb = smem_u32(shK);
    const uint32_t wb = smem_u32(shW);
    const uint32_t vb = smem_u32(shV);

    // ---- phase 0: widths (fp32 x, exact as before) ----
    {
        const float4* w4 = (const float4*)w_width;
        float4 wv[4];
        #pragma unroll
        for (int i = 0; i < 4; i++) wv[i] = w4[lane + 32 * i];
        const float bw = b_width[0];
        #pragma unroll
        for (int tt = 0; tt < 8; tt++) {
            const int t = wid * 8 + tt;
            const float4* xa = (const float4*)(x + (size_t)(tok0 + t) * CDIM);
            float s = 0.f;
            #pragma unroll
            for (int i = 0; i < 4; i++) {
                const float4 v = xa[lane + 32 * i];
                s += v.x * wv[i].x + v.y * wv[i].y + v.z * wv[i].z + v.w * wv[i].w;
            }
            #pragma unroll
            for (int o = 16; o > 0; o >>= 1) s += __shfl_xor_sync(0xffffffffu, s, o);
            if (lane == 0)
                shWidth[t] = 1.f / (1.f + expf(-(s + bw))) * (float)(KWIN - 1) + 1.f;
        }
    }

    // ---- phase 1: scores S = Q @ K^T ----
    const int m0 = (wid >> 1) * 16;
    const int n0 = (wid & 1) * 24;
    const uint32_t aLq = qb + (uint32_t)((m0 + (lane & 15)) * 144 + ((lane >> 4) & 1) * 16);
    const uint32_t bL4 = kb + (uint32_t)((n0 + ((lane >> 4) << 3) + (lane & 7)) * 144
                                         + ((lane >> 3) & 1) * 16);
    const uint32_t bL2 = kb + (uint32_t)((n0 + 16 + (lane & 7)) * 144 + ((lane >> 3) & 1) * 16);

    float s[3][4];
    #pragma unroll
    for (int f = 0; f < 3; f++)
        #pragma unroll
        for (int j = 0; j < 4; j++) s[f][j] = 0.f;

    for (int kc = 0; kc < 8; kc++) {
        __syncthreads();
        const int k0 = kc * 64;
        #pragma unroll
        for (int r = 0; r < 2; r++) {                 // Q: 256 chunks
            const int i = tid + 128 * r;
            const int row = i >> 3;
            const int c16 = (i & 7) * 16;
            cp16(qb + (uint32_t)(row * 144 + c16),
                 qkv + (size_t)(tok0 + row) * 3 * CDIM + k0 + (c16 >> 1));
        }
        #pragma unroll
        for (int r = 0; r < 3; r++) {                 // K: 384 chunks
            const int i = tid + 128 * r;
            const int row = i >> 3;
            const int c16 = (i & 7) * 16;
            const int gl = g0 + row;
            cp16z(kb + (uint32_t)(row * 144 + c16),
                  qkv + ((size_t)(gbase + gl) * 3 + 1) * CDIM + k0 + (c16 >> 1),
                  (gl >= 0 && gl < LSEQ));
        }
        CPCOMMIT();
        CPWAIT(0);
        __syncthreads();
        #pragma unroll
        for (int ks = 0; ks < 4; ks++) {
            const uint32_t ko = (uint32_t)(ks * 32);
            uint32_t a[4], b0[4], b2[2];
            ldsm_x4(a, aLq + ko);
            ldsm_x4(b0, bL4 + ko);
            ldsm_x2(b2, bL2 + ko);
            mma_f16(s[0], a, b0);
            mma_f16(s[1], a, b0 + 2);
            mma_f16(s[2], a, b2);
        }
    }

    // scores -> shS, zero shW
    #pragma unroll
    for (int f = 0; f < 3; f++) {
        const int r = m0 + (lane >> 2);
        const int c = n0 + f * 8 + (lane & 3) * 2;
        shS[r * 48 + c]           = s[f][0];
        shS[r * 48 + c + 1]       = s[f][1];
        shS[(r + 8) * 48 + c]     = s[f][2];
        shS[(r + 8) * 48 + c + 1] = s[f][3];
    }
    #pragma unroll
    for (int i = tid; i < ATB * APIT / 2; i += 128)
        ((uint32_t*)shW)[i] = 0;
    __syncthreads();

    // ---- phase 2: mask + softmax (one thread per token) ----
    if (tid < ATB) {
        const float width = shWidth[tid];
        const float scale = 0.044194173824159216f;
        float p[KWIN];
        float mx = -1e30f;
        #pragma unroll
        for (int j = 0; j < KWIN; j++) {
            const float rel = fabsf((float)j - (float)HALFK);
            const float m = 1.f / (1.f + expf(-(width - rel) * 5.f));
            const float v = shS[tid * 48 + tid + j] * scale - (1.f - m) * 10000.f;
            p[j] = v;
            mx = fmaxf(mx, v);
        }
        float d = 0.f;
        #pragma unroll
        for (int j = 0; j < KWIN; j++) { p[j] = expf(p[j] - mx); d += p[j]; }
        const float inv = 1.f / d;
        #pragma unroll
        for (int j = 0; j < KWIN; j++)
            shW[tid * APIT + tid + j] = __float2half(p[j] * inv);
    }

    // ---- phase 3: att = W @ V + v_self ----
    const int n0c = (wid & 1) * 32;
    const uint32_t aLw = wb + (uint32_t)((m0 + (lane & 15)) * 144 + ((lane >> 4) & 1) * 16);
    const int tg = lane >> 3, tl = lane & 7;     // trans-ldsm lane decomposition

    for (int nc = 0; nc < 8; nc++) {
        __syncthreads();
        const int ch0 = nc * 64;
        #pragma unroll
        for (int r = 0; r < 3; r++) {                 // V: 384 chunks
            const int i = tid + 128 * r;
            const int row = i >> 3;
            const int c16 = (i & 7) * 16;
            const int gl = g0 + row;
            cp16z(vb + (uint32_t)(row * 144 + c16),
                  qkv + ((size_t)(gbase + gl) * 3 + 2) * CDIM + ch0 + (c16 >> 1),
                  (gl >= 0 && gl < LSEQ));
        }
        CPCOMMIT();
        CPWAIT(0);
        __syncthreads();

        float o[4][4];
        #pragma unroll
        for (int f = 0; f < 4; f++)
            #pragma unroll
            for (int j = 0; j < 4; j++) o[f][j] = 0.f;

        #pragma unroll
        for (int ks = 0; ks < 3; ks++) {
            uint32_t a[4], bt[8];
            ldsm_x4(a, aLw + (uint32_t)(ks * 32));
            #pragma unroll
            for (int h = 0; h < 2; h++) {
                const int row = ks * 16 + (tg & 1) * 8 + tl;
                const int col = n0c + h * 16 + (tg >> 1) * 8;
                ldsm_x4_t(bt + h * 4, vb + (uint32_t)(row * 144 + col * 2));
            }
            mma_f16(o[0], a, bt + 0);
            mma_f16(o[1], a, bt + 2);
            mma_f16(o[2], a, bt + 4);
            mma_f16(o[3], a, bt + 6);
        }

        #pragma unroll
        for (int f = 0; f < 4; f++) {
            const int rr = m0 + (lane >> 2);
            const int cc = n0c + f * 8 + (lane & 3) * 2;
            const float2 v0 = __half22float2(*(const __half2*)(shV + (rr + 8) * APIT + cc));
            const float2 v1 = __half22float2(*(const __half2*)(shV + (rr + 16) * APIT + cc));
            *(__half2*)(att + (size_t)(tok0 + rr) * CDIM + ch0 + cc) =
                __floats2half2_rn(o[f][0] + v0.x, o[f][1] + v0.y);
            *(__half2*)(att + (size_t)(tok0 + rr + 8) * CDIM + ch0 + cc) =
                __floats2half2_rn(o[f][2] + v1.x, o[f][3] + v1.y);
        }
    }
}

// ---------------------------------------------------------------------------
extern "C" void kernel_launch(void* const* d_in, const int* in_sizes, int n_in,
                              void* d_out, int out_size)
{
    const float* x       = (const float*)d_in[0];
    const float* w_qkv   = (const float*)d_in[1];
    const float* w_width = (const float*)d_in[2];
    const float* b_width = (const float*)d_in[3];
    const float* w_out   = (const float*)d_in[4];
    float* out = (float*)d_out;

    __half* qkvh; cudaGetSymbolAddress((void**)&qkvh, g_qkvh);
    __half* xh;   cudaGetSymbolAddress((void**)&xh,   g_xh);
    __half* ah;   cudaGetSymbolAddress((void**)&ah,   g_ah);
    __half* wqh;  cudaGetSymbolAddress((void**)&wqh,  g_wqh);
    __half* woh;  cudaGetSymbolAddress((void**)&woh,  g_woh);

    cudaFuncSetAttribute(gemm_mma<__half>, cudaFuncAttributeMaxDynamicSharedMemorySize, GEMM_SMEM);
    cudaFuncSetAttribute(gemm_mma<float>,  cudaFuncAttributeMaxDynamicSharedMemorySize, GEMM_SMEM);

    // 0) fused prep: x->fp16 + both weight transposes
    prep_kernel<<<8192 + 768 + 256, 256>>>(x, xh, w_qkv, wqh, w_out, woh);

    // 1) qkv = x @ w_qkv   (fp16 in, fp16 out)
    {
        dim3 grid(3 * CDIM / 128, NTOK / 128);
        gemm_mma<__half><<<grid, 256, GEMM_SMEM>>>(xh, wqh, qkvh, 3 * CDIM);
    }

    // 2) MMA windowed attention -> att (fp16)
    attn_kernel<<<NTOK / ATB, 128>>>(x, w_width, b_width, ah);

    // 3) out = att @ w_out  (fp16 in, fp32 out)
    {
        dim3 grid(CDIM / 128, NTOK / 128);
        gemm_mma<float><<<grid, 256, GEMM_SMEM>>>(ah, woh, out, CDIM);
    }
}

// round 15
// speedup vs baseline: 1.4470x; 1.0167x over previous
#include <cuda_runtime.h>
#include <cuda_fp16.h>
#include <cstdint>

// Problem constants
#define BDIM 2
#define LSEQ 8192
#define CDIM 512
#define KWIN 17
#define HALFK 8
#define NTOK (BDIM * LSEQ)      // 16384

// ---------------------------------------------------------------------------
// Scratch (__device__ globals; no cudaMalloc allowed)
// ---------------------------------------------------------------------------
__device__ __half  g_qkvh[(size_t)NTOK * 3 * CDIM];    // 48 MB fp16 qkv
__device__ __half  g_xh[(size_t)NTOK * CDIM];          // x   -> fp16
__device__ __half  g_ah[(size_t)NTOK * CDIM];          // att -> fp16
__device__ __half  g_wqh[(size_t)3 * CDIM * CDIM];     // w_qkv^T fp16
__device__ __half  g_woh[(size_t)CDIM * CDIM];         // w_out^T fp16

// ---------------------------------------------------------------------------
// helpers
// ---------------------------------------------------------------------------
__device__ __forceinline__ uint32_t smem_u32(const void* p) {
    uint32_t a;
    asm("{ .reg .u64 t; cvta.to.shared.u64 t, %1; cvt.u32.u64 %0, t; }" : "=r"(a) : "l"(p));
    return a;
}
__device__ __forceinline__ void cp16(uint32_t dst, const void* src) {
    asm volatile("cp.async.cg.shared.global [%0], [%1], 16;" :: "r"(dst), "l"(src));
}
__device__ __forceinline__ void ldsm_x4(uint32_t* r, uint32_t addr) {
    asm volatile("ldmatrix.sync.aligned.m8n8.x4.shared.b16 {%0,%1,%2,%3}, [%4];"
                 : "=r"(r[0]), "=r"(r[1]), "=r"(r[2]), "=r"(r[3]) : "r"(addr));
}
__device__ __forceinline__ void ldsm_x2(uint32_t* r, uint32_t addr) {
    asm volatile("ldmatrix.sync.aligned.m8n8.x2.shared.b16 {%0,%1}, [%2];"
                 : "=r"(r[0]), "=r"(r[1]) : "r"(addr));
}
__device__ __forceinline__ void ldsm_x4_t(uint32_t* r, uint32_t addr) {
    asm volatile("ldmatrix.sync.aligned.m8n8.x4.trans.shared.b16 {%0,%1,%2,%3}, [%4];"
                 : "=r"(r[0]), "=r"(r[1]), "=r"(r[2]), "=r"(r[3]) : "r"(addr));
}
__device__ __forceinline__ void mma_f16(float* c, const uint32_t* a, const uint32_t* b) {
    asm volatile(
        "mma.sync.aligned.m16n8k16.row.col.f32.f16.f16.f32 "
        "{%0,%1,%2,%3}, {%4,%5,%6,%7}, {%8,%9}, {%0,%1,%2,%3};"
        : "+f"(c[0]), "+f"(c[1]), "+f"(c[2]), "+f"(c[3])
        : "r"(a[0]), "r"(a[1]), "r"(a[2]), "r"(a[3]), "r"(b[0]), "r"(b[1]));
}
#define CPWAIT(N) asm volatile("cp.async.wait_group %0;" :: "n"(N))
#define CPCOMMIT() asm volatile("cp.async.commit_group;" ::: "memory")

__device__ __forceinline__ void sts_zero16(uint32_t dst) {
    asm volatile("st.shared.v4.b32 [%0], {%1,%1,%1,%1};" :: "r"(dst), "r"(0) : "memory");
}
__device__ __forceinline__ void cp16z(uint32_t dst, const __half* src, bool valid) {
    if (valid) cp16(dst, src);
    else       sts_zero16(dst);
}

// ---------------------------------------------------------------------------
// Plain fp16 GEMM:  C = A @ B^T  (fp32 accum, OutT store)   [R13 winner]
// ---------------------------------------------------------------------------
#define GK       512
#define BK       64
#define NSTG     (GK / BK)          // 8
#define NBUF     3
#define PITCH    144
#define A_SZ     (128 * PITCH)      // 18432
#define STG_SZ   (2 * A_SZ)         // 36864
#define GEMM_SMEM (NBUF * STG_SZ)   // 110592

template <typename OutT>
__global__ __launch_bounds__(256, 2) void gemm_mma(
    const __half* __restrict__ A, const __half* __restrict__ B,
    OutT* __restrict__ C, int Ntot)
{
    extern __shared__ char smem[];
    const uint32_t sb = smem_u32(smem);
    const int tid  = threadIdx.x;
    const int wid  = tid >> 5;
    const int lane = tid & 31;
    const int bm = blockIdx.y * 128;
    const int bn = blockIdx.x * 128;
    const int warp_m = (wid >> 2) * 64;
    const int warp_n = (wid & 3) * 32;

    auto load_stage = [&](int s, int b) {
        const int k0 = s * BK;
        const uint32_t buf = sb + (uint32_t)b * STG_SZ;
        #pragma unroll
        for (int r = 0; r < 4; r++) {
            const int i   = tid + 256 * r;
            const int row = i >> 3;
            const int c16 = (i & 7) * 16;
            const uint32_t off = (uint32_t)(row * PITCH + c16);
            cp16(buf + off,        A + (size_t)(bm + row) * GK + k0 + (c16 >> 1));
            cp16(buf + A_SZ + off, B + (size_t)(bn + row) * GK + k0 + (c16 >> 1));
        }
        CPCOMMIT();
    };

    float acc[4][4][4];
    #pragma unroll
    for (int mi = 0; mi < 4; mi++)
        #pragma unroll
        for (int ni = 0; ni < 4; ni++)
            #pragma unroll
            for (int f = 0; f < 4; f++) acc[mi][ni][f] = 0.f;

    const uint32_t aLane = (uint32_t)((warp_m + (lane & 15)) * PITCH + ((lane >> 4) & 1) * 16);
    const uint32_t bLane4 = (uint32_t)((warp_n + ((lane >> 4) << 3) + (lane & 7)) * PITCH
                                       + ((lane >> 3) & 1) * 16);

    load_stage(0, 0);
    load_stage(1, 1);

    for (int s = 0; s < NSTG; s++) {
        const int b = s % NBUF;
        if (s + 1 < NSTG) CPWAIT(1);
        else              CPWAIT(0);
        __syncthreads();

        const uint32_t buf = sb + (uint32_t)b * STG_SZ;
        #pragma unroll
        for (int kk = 0; kk < 4; kk++) {
            const uint32_t ko = (uint32_t)(kk * 32);
            uint32_t ah[4][4], bh[4][2];
            #pragma unroll
            for (int mi = 0; mi < 4; mi++)
                ldsm_x4(ah[mi], buf + aLane + (uint32_t)(mi * 16 * PITCH) + ko);
            ldsm_x4(&bh[0][0], buf + A_SZ + bLane4 + ko);
            ldsm_x4(&bh[2][0], buf + A_SZ + bLane4 + (uint32_t)(16 * PITCH) + ko);
            #pragma unroll
            for (int mi = 0; mi < 4; mi++)
                #pragma unroll
                for (int ni = 0; ni < 4; ni++)
                    mma_f16(acc[mi][ni], ah[mi], bh[ni]);
        }

        if (s + 2 < NSTG) load_stage(s + 2, (s + 2) % NBUF);
    }

    const int er = lane >> 2;
    const int ec = (lane & 3) * 2;
    #pragma unroll
    for (int mi = 0; mi < 4; mi++) {
        #pragma unroll
        for (int ni = 0; ni < 4; ni++) {
            OutT* p0 = C + (size_t)(bm + warp_m + mi * 16 + er) * Ntot + bn + warp_n + ni * 8 + ec;
            if constexpr (sizeof(OutT) == 2) {
                *(__half2*)p0 = __floats2half2_rn(acc[mi][ni][0], acc[mi][ni][1]);
                *(__half2*)(p0 + (size_t)8 * Ntot) = __floats2half2_rn(acc[mi][ni][2], acc[mi][ni][3]);
            } else {
                *(float2*)p0                      = make_float2(acc[mi][ni][0], acc[mi][ni][1]);
                *(float2*)(p0 + (size_t)8 * Ntot) = make_float2(acc[mi][ni][2], acc[mi][ni][3]);
            }
        }
    }
}

// ---------------------------------------------------------------------------
// fused prep: x->fp16 (blocks 0..8191), w_qkv^T (next 768), w_out^T (next 256)
// ---------------------------------------------------------------------------
__global__ __launch_bounds__(256) void prep_kernel(
    const float* __restrict__ x,     __half* __restrict__ xh,
    const float* __restrict__ wq,    __half* __restrict__ wqh,
    const float* __restrict__ wo,    __half* __restrict__ woh)
{
    const int bid = blockIdx.x;
    const int tid = threadIdx.x;
    if (bid < 8192) {
        const size_t i = ((size_t)bid * 256 + tid) * 4;
        float4 v = *(const float4*)(x + i);
        *(__half2*)(xh + i)     = __floats2half2_rn(v.x, v.y);
        *(__half2*)(xh + i + 2) = __floats2half2_rn(v.z, v.w);
        return;
    }
    __shared__ float t[32][33];
    const float* w;  __half* wT;  int N, bx, by;
    if (bid < 8192 + 768) {
        w = wq; wT = wqh; N = 3 * CDIM;
        const int r = bid - 8192;
        bx = r % 48; by = r / 48;
    } else {
        w = wo; wT = woh; N = CDIM;
        const int r = bid - 8960;
        bx = r % 16; by = r / 16;
    }
    const int k0 = by * 32;
    const int n0 = bx * 32;
    const int tx = tid & 31, ty = tid >> 5;
    #pragma unroll
    for (int i = ty; i < 32; i += 8)
        t[i][tx] = w[(size_t)(k0 + i) * N + n0 + tx];
    __syncthreads();
    #pragma unroll
    for (int i = ty; i < 32; i += 8)
        wT[(size_t)(n0 + i) * CDIM + k0 + tx] = __float2half(t[tx][i]);
}

// ---------------------------------------------------------------------------
// MMA attention, double-buffered chunk loads: 128 threads / 32 tokens.
// Phase 1: S[32x48] = Q @ K_win^T (8 k-chunks, Q/K double buffered)
// Phase 2: per-token soft mask + softmax (V chunk 0 loads overlap this)
// Phase 3: att = W @ V + v_self (8 n-chunks, V double buffered)
// ---------------------------------------------------------------------------
#define ATB   32
#define AWIN  48
#define APIT  72          // halves per row (144 B)

__global__ __launch_bounds__(128) void attn_kernel(const float* __restrict__ x,
                                                   const float* __restrict__ w_width,
                                                   const float* __restrict__ b_width,
                                                   __half* __restrict__ att)
{
    __shared__ __align__(128) __half shQ[2][ATB * APIT];    // 9216 B
    __shared__ __align__(128) __half shK[2][AWIN * APIT];   // 13824 B
    __shared__ __align__(128) __half shV[2][AWIN * APIT];   // 13824 B
    __shared__ __align__(128) float  shS[ATB * 48];         // 6144 B
    __shared__ __align__(128) __half shW[ATB * APIT];       // 4608 B
    __shared__ float shWidth[ATB];                          // total 47744 B

    const int tid  = threadIdx.x;
    const int wid  = tid >> 5;
    const int lane = tid & 31;
    const int tok0 = blockIdx.x * ATB;
    const int l0   = tok0 & (LSEQ - 1);
    const int g0   = l0 - HALFK;
    const size_t gbase = (size_t)(tok0 >> 13) * LSEQ;

    const __half* qkv = g_qkvh;
    const uint32_t wb = smem_u32(shW);

    auto load_qk = [&](int kc, int b) {
        const int k0 = kc * 64;
        const uint32_t qb = smem_u32(shQ[b]);
        const uint32_t kb = smem_u32(shK[b]);
        #pragma unroll
        for (int r = 0; r < 2; r++) {
            const int i = tid + 128 * r;
            const int row = i >> 3;
            const int c16 = (i & 7) * 16;
            cp16(qb + (uint32_t)(row * 144 + c16),
                 qkv + (size_t)(tok0 + row) * 3 * CDIM + k0 + (c16 >> 1));
        }
        #pragma unroll
        for (int r = 0; r < 3; r++) {
            const int i = tid + 128 * r;
            const int row = i >> 3;
            const int c16 = (i & 7) * 16;
            const int gl = g0 + row;
            cp16z(kb + (uint32_t)(row * 144 + c16),
                  qkv + ((size_t)(gbase + gl) * 3 + 1) * CDIM + k0 + (c16 >> 1),
                  (gl >= 0 && gl < LSEQ));
        }
        CPCOMMIT();
    };
    auto load_v = [&](int nc, int b) {
        const int ch0 = nc * 64;
        const uint32_t vb = smem_u32(shV[b]);
        #pragma unroll
        for (int r = 0; r < 3; r++) {
            const int i = tid + 128 * r;
            const int row = i >> 3;
            const int c16 = (i & 7) * 16;
            const int gl = g0 + row;
            cp16z(vb + (uint32_t)(row * 144 + c16),
                  qkv + ((size_t)(gbase + gl) * 3 + 2) * CDIM + ch0 + (c16 >> 1),
                  (gl >= 0 && gl < LSEQ));
        }
        CPCOMMIT();
    };

    // ---- phase 0: widths ----
    {
        const float4* w4 = (const float4*)w_width;
        float4 wv[4];
        #pragma unroll
        for (int i = 0; i < 4; i++) wv[i] = w4[lane + 32 * i];
        const float bw = b_width[0];
        #pragma unroll
        for (int tt = 0; tt < 8; tt++) {
            const int t = wid * 8 + tt;
            const float4* xa = (const float4*)(x + (size_t)(tok0 + t) * CDIM);
            float s = 0.f;
            #pragma unroll
            for (int i = 0; i < 4; i++) {
                const float4 v = xa[lane + 32 * i];
                s += v.x * wv[i].x + v.y * wv[i].y + v.z * wv[i].z + v.w * wv[i].w;
            }
            #pragma unroll
            for (int o = 16; o > 0; o >>= 1) s += __shfl_xor_sync(0xffffffffu, s, o);
            if (lane == 0)
                shWidth[t] = 1.f / (1.f + expf(-(s + bw))) * (float)(KWIN - 1) + 1.f;
        }
    }

    // ---- phase 1: scores S = Q @ K^T (double buffered) ----
    const int m0 = (wid >> 1) * 16;
    const int n0 = (wid & 1) * 24;
    const uint32_t aOffQ = (uint32_t)((m0 + (lane & 15)) * 144 + ((lane >> 4) & 1) * 16);
    const uint32_t bOff4 = (uint32_t)((n0 + ((lane >> 4) << 3) + (lane & 7)) * 144
                                      + ((lane >> 3) & 1) * 16);
    const uint32_t bOff2 = (uint32_t)((n0 + 16 + (lane & 7)) * 144 + ((lane >> 3) & 1) * 16);

    float s[3][4];
    #pragma unroll
    for (int f = 0; f < 3; f++)
        #pragma unroll
        for (int j = 0; j < 4; j++) s[f][j] = 0.f;

    load_qk(0, 0);
    for (int kc = 0; kc < 8; kc++) {
        const int b = kc & 1;
        CPWAIT(0);
        __syncthreads();
        if (kc + 1 < 8) load_qk(kc + 1, b ^ 1);

        const uint32_t qb = smem_u32(shQ[b]);
        const uint32_t kb = smem_u32(shK[b]);
        #pragma unroll
        for (int ks = 0; ks < 4; ks++) {
            const uint32_t ko = (uint32_t)(ks * 32);
            uint32_t a[4], b0[4], b2[2];
            ldsm_x4(a, qb + aOffQ + ko);
            ldsm_x4(b0, kb + bOff4 + ko);
            ldsm_x2(b2, kb + bOff2 + ko);
            mma_f16(s[0], a, b0);
            mma_f16(s[1], a, b0 + 2);
            mma_f16(s[2], a, b2);
        }
    }
    // V chunk 0 loads overlap the softmax below
    load_v(0, 0);

    // scores -> shS, zero shW
    #pragma unroll
    for (int f = 0; f < 3; f++) {
        const int r = m0 + (lane >> 2);
        const int c = n0 + f * 8 + (lane & 3) * 2;
        shS[r * 48 + c]           = s[f][0];
        shS[r * 48 + c + 1]       = s[f][1];
        shS[(r + 8) * 48 + c]     = s[f][2];
        shS[(r + 8) * 48 + c + 1] = s[f][3];
    }
    #pragma unroll
    for (int i = tid; i < ATB * APIT / 2; i += 128)
        ((uint32_t*)shW)[i] = 0;
    __syncthreads();

    // ---- phase 2: mask + softmax (one thread per token) ----
    if (tid < ATB) {
        const float width = shWidth[tid];
        const float scale = 0.044194173824159216f;
        float p[KWIN];
        float mx = -1e30f;
        #pragma unroll
        for (int j = 0; j < KWIN; j++) {
            const float rel = fabsf((float)j - (float)HALFK);
            const float m = 1.f / (1.f + expf(-(width - rel) * 5.f));
            const float v = shS[tid * 48 + tid + j] * scale - (1.f - m) * 10000.f;
            p[j] = v;
            mx = fmaxf(mx, v);
        }
        float d = 0.f;
        #pragma unroll
        for (int j = 0; j < KWIN; j++) { p[j] = expf(p[j] - mx); d += p[j]; }
        const float inv = 1.f / d;
        #pragma unroll
        for (int j = 0; j < KWIN; j++)
            shW[tid * APIT + tid + j] = __float2half(p[j] * inv);
    }

    // ---- phase 3: att = W @ V + v_self (V double buffered) ----
    const int n0c = (wid & 1) * 32;
    const uint32_t aLw = wb + (uint32_t)((m0 + (lane & 15)) * 144 + ((lane >> 4) & 1) * 16);
    const int tg = lane >> 3, tl = lane & 7;

    for (int nc = 0; nc < 8; nc++) {
        const int b = nc & 1;
        CPWAIT(0);
        __syncthreads();
        if (nc + 1 < 8) load_v(nc + 1, b ^ 1);

        const int ch0 = nc * 64;
        const uint32_t vb = smem_u32(shV[b]);
        const __half* shVc = shV[b];

        float o[4][4];
        #pragma unroll
        for (int f = 0; f < 4; f++)
            #pragma unroll
            for (int j = 0; j < 4; j++) o[f][j] = 0.f;

        #pragma unroll
        for (int ks = 0; ks < 3; ks++) {
            uint32_t a[4], bt[8];
            ldsm_x4(a, aLw + (uint32_t)(ks * 32));
            #pragma unroll
            for (int h = 0; h < 2; h++) {
                const int row = ks * 16 + (tg & 1) * 8 + tl;
                const int col = n0c + h * 16 + (tg >> 1) * 8;
                ldsm_x4_t(bt + h * 4, vb + (uint32_t)(row * 144 + col * 2));
            }
            mma_f16(o[0], a, bt + 0);
            mma_f16(o[1], a, bt + 2);
            mma_f16(o[2], a, bt + 4);
            mma_f16(o[3], a, bt + 6);
        }

        #pragma unroll
        for (int f = 0; f < 4; f++) {
            const int rr = m0 + (lane >> 2);
            const int cc = n0c + f * 8 + (lane & 3) * 2;
            const float2 v0 = __half22float2(*(const __half2*)(shVc + (rr + 8) * APIT + cc));
            const float2 v1 = __half22float2(*(const __half2*)(shVc + (rr + 16) * APIT + cc));
            *(__half2*)(att + (size_t)(tok0 + rr) * CDIM + ch0 + cc) =
                __floats2half2_rn(o[f][0] + v0.x, o[f][1] + v0.y);
            *(__half2*)(att + (size_t)(tok0 + rr + 8) * CDIM + ch0 + cc) =
                __floats2half2_rn(o[f][2] + v1.x, o[f][3] + v1.y);
        }
    }
}

// ---------------------------------------------------------------------------
extern "C" void kernel_launch(void* const* d_in, const int* in_sizes, int n_in,
                              void* d_out, int out_size)
{
    const float* x       = (const float*)d_in[0];
    const float* w_qkv   = (const float*)d_in[1];
    const float* w_width = (const float*)d_in[2];
    const float* b_width = (const float*)d_in[3];
    const float* w_out   = (const float*)d_in[4];
    float* out = (float*)d_out;

    __half* qkvh; cudaGetSymbolAddress((void**)&qkvh, g_qkvh);
    __half* xh;   cudaGetSymbolAddress((void**)&xh,   g_xh);
    __half* ah;   cudaGetSymbolAddress((void**)&ah,   g_ah);
    __half* wqh;  cudaGetSymbolAddress((void**)&wqh,  g_wqh);
    __half* woh;  cudaGetSymbolAddress((void**)&woh,  g_woh);

    cudaFuncSetAttribute(gemm_mma<__half>, cudaFuncAttributeMaxDynamicSharedMemorySize, GEMM_SMEM);
    cudaFuncSetAttribute(gemm_mma<float>,  cudaFuncAttributeMaxDynamicSharedMemorySize, GEMM_SMEM);

    // 0) fused prep: x->fp16 + both weight transposes
    prep_kernel<<<8192 + 768 + 256, 256>>>(x, xh, w_qkv, wqh, w_out, woh);

    // 1) qkv = x @ w_qkv   (fp16 in, fp16 out)
    {
        dim3 grid(3 * CDIM / 128, NTOK / 128);
        gemm_mma<__half><<<grid, 256, GEMM_SMEM>>>(xh, wqh, qkvh, 3 * CDIM);
    }

    // 2) MMA windowed attention (double-buffered) -> att (fp16)
    attn_kernel<<<NTOK / ATB, 128>>>(x, w_width, b_width, ah);

    // 3) out = att @ w_out  (fp16 in, fp32 out)
    {
        dim3 grid(CDIM / 128, NTOK / 128);
        gemm_mma<float><<<grid, 256, GEMM_SMEM>>>(ah, woh, out, CDIM);
    }
}

// round 16
// speedup vs baseline: 1.5128x; 1.0455x over previous
#include <cuda_runtime.h>
#include <cuda_fp16.h>
#include <cstdint>

// Problem constants
#define BDIM 2
#define LSEQ 8192
#define CDIM 512
#define KWIN 17
#define HALFK 8
#define NTOK (BDIM * LSEQ)      // 16384

// ---------------------------------------------------------------------------
// Scratch (__device__ globals; no cudaMalloc allowed)
// ---------------------------------------------------------------------------
__device__ __half  g_qkvh[(size_t)NTOK * 3 * CDIM];    // 48 MB fp16 qkv
__device__ __half  g_xh[(size_t)NTOK * CDIM];          // x   -> fp16
__device__ __half  g_ah[(size_t)NTOK * CDIM];          // att -> fp16
__device__ __half  g_wqh[(size_t)3 * CDIM * CDIM];     // w_qkv^T fp16
__device__ __half  g_woh[(size_t)CDIM * CDIM];         // w_out^T fp16
__device__ float   g_width[NTOK];                      // precomputed widths

// ---------------------------------------------------------------------------
// helpers
// ---------------------------------------------------------------------------
__device__ __forceinline__ uint32_t smem_u32(const void* p) {
    uint32_t a;
    asm("{ .reg .u64 t; cvta.to.shared.u64 t, %1; cvt.u32.u64 %0, t; }" : "=r"(a) : "l"(p));
    return a;
}
__device__ __forceinline__ void cp16(uint32_t dst, const void* src) {
    asm volatile("cp.async.cg.shared.global [%0], [%1], 16;" :: "r"(dst), "l"(src));
}
__device__ __forceinline__ void ldsm_x4(uint32_t* r, uint32_t addr) {
    asm volatile("ldmatrix.sync.aligned.m8n8.x4.shared.b16 {%0,%1,%2,%3}, [%4];"
                 : "=r"(r[0]), "=r"(r[1]), "=r"(r[2]), "=r"(r[3]) : "r"(addr));
}
__device__ __forceinline__ void ldsm_x2(uint32_t* r, uint32_t addr) {
    asm volatile("ldmatrix.sync.aligned.m8n8.x2.shared.b16 {%0,%1}, [%2];"
                 : "=r"(r[0]), "=r"(r[1]) : "r"(addr));
}
__device__ __forceinline__ void ldsm_x4_t(uint32_t* r, uint32_t addr) {
    asm volatile("ldmatrix.sync.aligned.m8n8.x4.trans.shared.b16 {%0,%1,%2,%3}, [%4];"
                 : "=r"(r[0]), "=r"(r[1]), "=r"(r[2]), "=r"(r[3]) : "r"(addr));
}
__device__ __forceinline__ void mma_f16(float* c, const uint32_t* a, const uint32_t* b) {
    asm volatile(
        "mma.sync.aligned.m16n8k16.row.col.f32.f16.f16.f32 "
        "{%0,%1,%2,%3}, {%4,%5,%6,%7}, {%8,%9}, {%0,%1,%2,%3};"
        : "+f"(c[0]), "+f"(c[1]), "+f"(c[2]), "+f"(c[3])
        : "r"(a[0]), "r"(a[1]), "r"(a[2]), "r"(a[3]), "r"(b[0]), "r"(b[1]));
}
#define CPWAIT(N) asm volatile("cp.async.wait_group %0;" :: "n"(N))
#define CPCOMMIT() asm volatile("cp.async.commit_group;" ::: "memory")

__device__ __forceinline__ void sts_zero16(uint32_t dst) {
    asm volatile("st.shared.v4.b32 [%0], {%1,%1,%1,%1};" :: "r"(dst), "r"(0) : "memory");
}
__device__ __forceinline__ void cp16z(uint32_t dst, const __half* src, bool valid) {
    if (valid) cp16(dst, src);
    else       sts_zero16(dst);
}

// ---------------------------------------------------------------------------
// Plain fp16 GEMM:  C = A @ B^T  (fp32 accum, OutT store)   [R13 winner]
// ---------------------------------------------------------------------------
#define GK       512
#define BK       64
#define NSTG     (GK / BK)          // 8
#define NBUF     3
#define PITCH    144
#define A_SZ     (128 * PITCH)      // 18432
#define STG_SZ   (2 * A_SZ)         // 36864
#define GEMM_SMEM (NBUF * STG_SZ)   // 110592

template <typename OutT>
__global__ __launch_bounds__(256, 2) void gemm_mma(
    const __half* __restrict__ A, const __half* __restrict__ B,
    OutT* __restrict__ C, int Ntot)
{
    extern __shared__ char smem[];
    const uint32_t sb = smem_u32(smem);
    const int tid  = threadIdx.x;
    const int wid  = tid >> 5;
    const int lane = tid & 31;
    const int bm = blockIdx.y * 128;
    const int bn = blockIdx.x * 128;
    const int warp_m = (wid >> 2) * 64;
    const int warp_n = (wid & 3) * 32;

    auto load_stage = [&](int s, int b) {
        const int k0 = s * BK;
        const uint32_t buf = sb + (uint32_t)b * STG_SZ;
        #pragma unroll
        for (int r = 0; r < 4; r++) {
            const int i   = tid + 256 * r;
            const int row = i >> 3;
            const int c16 = (i & 7) * 16;
            const uint32_t off = (uint32_t)(row * PITCH + c16);
            cp16(buf + off,        A + (size_t)(bm + row) * GK + k0 + (c16 >> 1));
            cp16(buf + A_SZ + off, B + (size_t)(bn + row) * GK + k0 + (c16 >> 1));
        }
        CPCOMMIT();
    };

    float acc[4][4][4];
    #pragma unroll
    for (int mi = 0; mi < 4; mi++)
        #pragma unroll
        for (int ni = 0; ni < 4; ni++)
            #pragma unroll
            for (int f = 0; f < 4; f++) acc[mi][ni][f] = 0.f;

    const uint32_t aLane = (uint32_t)((warp_m + (lane & 15)) * PITCH + ((lane >> 4) & 1) * 16);
    const uint32_t bLane4 = (uint32_t)((warp_n + ((lane >> 4) << 3) + (lane & 7)) * PITCH
                                       + ((lane >> 3) & 1) * 16);

    load_stage(0, 0);
    load_stage(1, 1);

    for (int s = 0; s < NSTG; s++) {
        const int b = s % NBUF;
        if (s + 1 < NSTG) CPWAIT(1);
        else              CPWAIT(0);
        __syncthreads();

        const uint32_t buf = sb + (uint32_t)b * STG_SZ;
        #pragma unroll
        for (int kk = 0; kk < 4; kk++) {
            const uint32_t ko = (uint32_t)(kk * 32);
            uint32_t ah[4][4], bh[4][2];
            #pragma unroll
            for (int mi = 0; mi < 4; mi++)
                ldsm_x4(ah[mi], buf + aLane + (uint32_t)(mi * 16 * PITCH) + ko);
            ldsm_x4(&bh[0][0], buf + A_SZ + bLane4 + ko);
            ldsm_x4(&bh[2][0], buf + A_SZ + bLane4 + (uint32_t)(16 * PITCH) + ko);
            #pragma unroll
            for (int mi = 0; mi < 4; mi++)
                #pragma unroll
                for (int ni = 0; ni < 4; ni++)
                    mma_f16(acc[mi][ni], ah[mi], bh[ni]);
        }

        if (s + 2 < NSTG) load_stage(s + 2, (s + 2) % NBUF);
    }

    const int er = lane >> 2;
    const int ec = (lane & 3) * 2;
    #pragma unroll
    for (int mi = 0; mi < 4; mi++) {
        #pragma unroll
        for (int ni = 0; ni < 4; ni++) {
            OutT* p0 = C + (size_t)(bm + warp_m + mi * 16 + er) * Ntot + bn + warp_n + ni * 8 + ec;
            if constexpr (sizeof(OutT) == 2) {
                *(__half2*)p0 = __floats2half2_rn(acc[mi][ni][0], acc[mi][ni][1]);
                *(__half2*)(p0 + (size_t)8 * Ntot) = __floats2half2_rn(acc[mi][ni][2], acc[mi][ni][3]);
            } else {
                *(float2*)p0                      = make_float2(acc[mi][ni][0], acc[mi][ni][1]);
                *(float2*)(p0 + (size_t)8 * Ntot) = make_float2(acc[mi][ni][2], acc[mi][ni][3]);
            }
        }
    }
}

// ---------------------------------------------------------------------------
// fused prep: x->fp16 + per-token width (blocks 0..8191, 2 tokens/block),
//             w_qkv^T (next 768), w_out^T (next 256)
// ---------------------------------------------------------------------------
__global__ __launch_bounds__(256) void prep_kernel(
    const float* __restrict__ x,     __half* __restrict__ xh,
    const float* __restrict__ wq,    __half* __restrict__ wqh,
    const float* __restrict__ wo,    __half* __restrict__ woh,
    const float* __restrict__ w_width, const float* __restrict__ b_width,
    float* __restrict__ width)
{
    const int bid = blockIdx.x;
    const int tid = threadIdx.x;
    if (bid < 8192) {
        // 1024 consecutive floats = tokens 2*bid, 2*bid+1
        const size_t i = ((size_t)bid * 256 + tid) * 4;
        float4 v = *(const float4*)(x + i);
        *(__half2*)(xh + i)     = __floats2half2_rn(v.x, v.y);
        *(__half2*)(xh + i + 2) = __floats2half2_rn(v.z, v.w);

        // width partial: this thread's 4 dims of token (tid<128 ? t0 : t1)
        const float4 wv = ((const float4*)w_width)[tid & 127];
        float s = v.x * wv.x + v.y * wv.y + v.z * wv.z + v.w * wv.w;
        #pragma unroll
        for (int o = 16; o > 0; o >>= 1) s += __shfl_xor_sync(0xffffffffu, s, o);
        __shared__ float red[8];
        if ((tid & 31) == 0) red[tid >> 5] = s;
        __syncthreads();
        if (tid < 2) {
            const float tot = red[tid * 4] + red[tid * 4 + 1] + red[tid * 4 + 2] + red[tid * 4 + 3];
            width[bid * 2 + tid] =
                1.f / (1.f + expf(-(tot + b_width[0]))) * (float)(KWIN - 1) + 1.f;
        }
        return;
    }
    __shared__ float t[32][33];
    const float* w;  __half* wT;  int N, bx, by;
    if (bid < 8192 + 768) {
        w = wq; wT = wqh; N = 3 * CDIM;
        const int r = bid - 8192;
        bx = r % 48; by = r / 48;
    } else {
        w = wo; wT = woh; N = CDIM;
        const int r = bid - 8960;
        bx = r % 16; by = r / 16;
    }
    const int k0 = by * 32;
    const int n0 = bx * 32;
    const int tx = tid & 31, ty = tid >> 5;
    #pragma unroll
    for (int i = ty; i < 32; i += 8)
        t[i][tx] = w[(size_t)(k0 + i) * N + n0 + tx];
    __syncthreads();
    #pragma unroll
    for (int i = ty; i < 32; i += 8)
        wT[(size_t)(n0 + i) * CDIM + k0 + tx] = __float2half(t[tx][i]);
}

// ---------------------------------------------------------------------------
// MMA attention, double-buffered chunk loads: 128 threads / 32 tokens.
// Widths precomputed by prep.  Phase 1: S = Q@K^T; phase 2: mask+softmax;
// phase 3: att = W@V + v_self.
// ---------------------------------------------------------------------------
#define ATB   32
#define AWIN  48
#define APIT  72          // halves per row (144 B)

__global__ __launch_bounds__(128) void attn_kernel(const float* __restrict__ width,
                                                   __half* __restrict__ att)
{
    __shared__ __align__(128) __half shQ[2][ATB * APIT];
    __shared__ __align__(128) __half shK[2][AWIN * APIT];
    __shared__ __align__(128) __half shV[2][AWIN * APIT];
    __shared__ __align__(128) float  shS[ATB * 48];
    __shared__ __align__(128) __half shW[ATB * APIT];
    __shared__ float shWidth[ATB];

    const int tid  = threadIdx.x;
    const int wid  = tid >> 5;
    const int lane = tid & 31;
    const int tok0 = blockIdx.x * ATB;
    const int l0   = tok0 & (LSEQ - 1);
    const int g0   = l0 - HALFK;
    const size_t gbase = (size_t)(tok0 >> 13) * LSEQ;

    const __half* qkv = g_qkvh;
    const uint32_t wb = smem_u32(shW);

    auto load_qk = [&](int kc, int b) {
        const int k0 = kc * 64;
        const uint32_t qb = smem_u32(shQ[b]);
        const uint32_t kb = smem_u32(shK[b]);
        #pragma unroll
        for (int r = 0; r < 2; r++) {
            const int i = tid + 128 * r;
            const int row = i >> 3;
            const int c16 = (i & 7) * 16;
            cp16(qb + (uint32_t)(row * 144 + c16),
                 qkv + (size_t)(tok0 + row) * 3 * CDIM + k0 + (c16 >> 1));
        }
        #pragma unroll
        for (int r = 0; r < 3; r++) {
            const int i = tid + 128 * r;
            const int row = i >> 3;
            const int c16 = (i & 7) * 16;
            const int gl = g0 + row;
            cp16z(kb + (uint32_t)(row * 144 + c16),
                  qkv + ((size_t)(gbase + gl) * 3 + 1) * CDIM + k0 + (c16 >> 1),
                  (gl >= 0 && gl < LSEQ));
        }
        CPCOMMIT();
    };
    auto load_v = [&](int nc, int b) {
        const int ch0 = nc * 64;
        const uint32_t vb = smem_u32(shV[b]);
        #pragma unroll
        for (int r = 0; r < 3; r++) {
            const int i = tid + 128 * r;
            const int row = i >> 3;
            const int c16 = (i & 7) * 16;
            const int gl = g0 + row;
            cp16z(vb + (uint32_t)(row * 144 + c16),
                  qkv + ((size_t)(gbase + gl) * 3 + 2) * CDIM + ch0 + (c16 >> 1),
                  (gl >= 0 && gl < LSEQ));
        }
        CPCOMMIT();
    };

    load_qk(0, 0);
    if (tid < ATB) shWidth[tid] = width[tok0 + tid];

    // ---- phase 1: scores S = Q @ K^T (double buffered) ----
    const int m0 = (wid >> 1) * 16;
    const int n0 = (wid & 1) * 24;
    const uint32_t aOffQ = (uint32_t)((m0 + (lane & 15)) * 144 + ((lane >> 4) & 1) * 16);
    const uint32_t bOff4 = (uint32_t)((n0 + ((lane >> 4) << 3) + (lane & 7)) * 144
                                      + ((lane >> 3) & 1) * 16);
    const uint32_t bOff2 = (uint32_t)((n0 + 16 + (lane & 7)) * 144 + ((lane >> 3) & 1) * 16);

    float s[3][4];
    #pragma unroll
    for (int f = 0; f < 3; f++)
        #pragma unroll
        for (int j = 0; j < 4; j++) s[f][j] = 0.f;

    for (int kc = 0; kc < 8; kc++) {
        const int b = kc & 1;
        CPWAIT(0);
        __syncthreads();
        if (kc + 1 < 8) load_qk(kc + 1, b ^ 1);

        const uint32_t qb = smem_u32(shQ[b]);
        const uint32_t kb = smem_u32(shK[b]);
        #pragma unroll
        for (int ks = 0; ks < 4; ks++) {
            const uint32_t ko = (uint32_t)(ks * 32);
            uint32_t a[4], b0[4], b2[2];
            ldsm_x4(a, qb + aOffQ + ko);
            ldsm_x4(b0, kb + bOff4 + ko);
            ldsm_x2(b2, kb + bOff2 + ko);
            mma_f16(s[0], a, b0);
            mma_f16(s[1], a, b0 + 2);
            mma_f16(s[2], a, b2);
        }
    }
    // V chunk 0 loads overlap the softmax below
    load_v(0, 0);

    // scores -> shS, zero shW
    #pragma unroll
    for (int f = 0; f < 3; f++) {
        const int r = m0 + (lane >> 2);
        const int c = n0 + f * 8 + (lane & 3) * 2;
        shS[r * 48 + c]           = s[f][0];
        shS[r * 48 + c + 1]       = s[f][1];
        shS[(r + 8) * 48 + c]     = s[f][2];
        shS[(r + 8) * 48 + c + 1] = s[f][3];
    }
    #pragma unroll
    for (int i = tid; i < ATB * APIT / 2; i += 128)
        ((uint32_t*)shW)[i] = 0;
    __syncthreads();

    // ---- phase 2: mask + softmax (one thread per token) ----
    if (tid < ATB) {
        const float width_t = shWidth[tid];
        const float scale = 0.044194173824159216f;
        float p[KWIN];
        float mx = -1e30f;
        #pragma unroll
        for (int j = 0; j < KWIN; j++) {
            const float rel = fabsf((float)j - (float)HALFK);
            const float m = 1.f / (1.f + expf(-(width_t - rel) * 5.f));
            const float v = shS[tid * 48 + tid + j] * scale - (1.f - m) * 10000.f;
            p[j] = v;
            mx = fmaxf(mx, v);
        }
        float d = 0.f;
        #pragma unroll
        for (int j = 0; j < KWIN; j++) { p[j] = expf(p[j] - mx); d += p[j]; }
        const float inv = 1.f / d;
        #pragma unroll
        for (int j = 0; j < KWIN; j++)
            shW[tid * APIT + tid + j] = __float2half(p[j] * inv);
    }

    // ---- phase 3: att = W @ V + v_self (V double buffered) ----
    const int n0c = (wid & 1) * 32;
    const uint32_t aLw = wb + (uint32_t)((m0 + (lane & 15)) * 144 + ((lane >> 4) & 1) * 16);
    const int tg = lane >> 3, tl = lane & 7;

    for (int nc = 0; nc < 8; nc++) {
        const int b = nc & 1;
        CPWAIT(0);
        __syncthreads();
        if (nc + 1 < 8) load_v(nc + 1, b ^ 1);

        const int ch0 = nc * 64;
        const uint32_t vb = smem_u32(shV[b]);
        const __half* shVc = shV[b];

        float o[4][4];
        #pragma unroll
        for (int f = 0; f < 4; f++)
            #pragma unroll
            for (int j = 0; j < 4; j++) o[f][j] = 0.f;

        #pragma unroll
        for (int ks = 0; ks < 3; ks++) {
            uint32_t a[4], bt[8];
            ldsm_x4(a, aLw + (uint32_t)(ks * 32));
            #pragma unroll
            for (int h = 0; h < 2; h++) {
                const int row = ks * 16 + (tg & 1) * 8 + tl;
                const int col = n0c + h * 16 + (tg >> 1) * 8;
                ldsm_x4_t(bt + h * 4, vb + (uint32_t)(row * 144 + col * 2));
            }
            mma_f16(o[0], a, bt + 0);
            mma_f16(o[1], a, bt + 2);
            mma_f16(o[2], a, bt + 4);
            mma_f16(o[3], a, bt + 6);
        }

        #pragma unroll
        for (int f = 0; f < 4; f++) {
            const int rr = m0 + (lane >> 2);
            const int cc = n0c + f * 8 + (lane & 3) * 2;
            const float2 v0 = __half22float2(*(const __half2*)(shVc + (rr + 8) * APIT + cc));
            const float2 v1 = __half22float2(*(const __half2*)(shVc + (rr + 16) * APIT + cc));
            *(__half2*)(att + (size_t)(tok0 + rr) * CDIM + ch0 + cc) =
                __floats2half2_rn(o[f][0] + v0.x, o[f][1] + v0.y);
            *(__half2*)(att + (size_t)(tok0 + rr + 8) * CDIM + ch0 + cc) =
                __floats2half2_rn(o[f][2] + v1.x, o[f][3] + v1.y);
        }
    }
}

// ---------------------------------------------------------------------------
extern "C" void kernel_launch(void* const* d_in, const int* in_sizes, int n_in,
                              void* d_out, int out_size)
{
    const float* x       = (const float*)d_in[0];
    const float* w_qkv   = (const float*)d_in[1];
    const float* w_width = (const float*)d_in[2];
    const float* b_width = (const float*)d_in[3];
    const float* w_out   = (const float*)d_in[4];
    float* out = (float*)d_out;

    __half* qkvh; cudaGetSymbolAddress((void**)&qkvh, g_qkvh);
    __half* xh;   cudaGetSymbolAddress((void**)&xh,   g_xh);
    __half* ah;   cudaGetSymbolAddress((void**)&ah,   g_ah);
    __half* wqh;  cudaGetSymbolAddress((void**)&wqh,  g_wqh);
    __half* woh;  cudaGetSymbolAddress((void**)&woh,  g_woh);
    float*  wdt;  cudaGetSymbolAddress((void**)&wdt,  g_width);

    cudaFuncSetAttribute(gemm_mma<__half>, cudaFuncAttributeMaxDynamicSharedMemorySize, GEMM_SMEM);
    cudaFuncSetAttribute(gemm_mma<float>,  cudaFuncAttributeMaxDynamicSharedMemorySize, GEMM_SMEM);

    // 0) fused prep: x->fp16 + widths + both weight transposes
    prep_kernel<<<8192 + 768 + 256, 256>>>(x, xh, w_qkv, wqh, w_out, woh,
                                           w_width, b_width, wdt);

    // 1) qkv = x @ w_qkv   (fp16 in, fp16 out)
    {
        dim3 grid(3 * CDIM / 128, NTOK / 128);
        gemm_mma<__half><<<grid, 256, GEMM_SMEM>>>(xh, wqh, qkvh, 3 * CDIM);
    }

    // 2) MMA windowed attention -> att (fp16)
    attn_kernel<<<NTOK / ATB, 128>>>(wdt, ah);

    // 3) out = att @ w_out  (fp16 in, fp32 out)
    {
        dim3 grid(CDIM / 128, NTOK / 128);
        gemm_mma<float><<<grid, 256, GEMM_SMEM>>>(ah, woh, out, CDIM);
    }
}

// round 17
// speedup vs baseline: 1.5171x; 1.0028x over previous
#include <cuda_runtime.h>
#include <cuda_fp16.h>
#include <cstdint>

// Problem constants
#define BDIM 2
#define LSEQ 8192
#define CDIM 512
#define KWIN 17
#define HALFK 8
#define NTOK (BDIM * LSEQ)      // 16384

// ---------------------------------------------------------------------------
// Scratch (__device__ globals; no cudaMalloc allowed)
// ---------------------------------------------------------------------------
__device__ __half  g_qkvh[(size_t)NTOK * 3 * CDIM];    // 48 MB fp16 qkv
__device__ __half  g_xh[(size_t)NTOK * CDIM];          // x   -> fp16
__device__ __half  g_ah[(size_t)NTOK * CDIM];          // att -> fp16
__device__ __half  g_wqh[(size_t)3 * CDIM * CDIM];     // w_qkv^T fp16
__device__ __half  g_woh[(size_t)CDIM * CDIM];         // w_out^T fp16
__device__ float   g_width[NTOK];                      // precomputed widths

// ---------------------------------------------------------------------------
// helpers
// ---------------------------------------------------------------------------
__device__ __forceinline__ uint32_t smem_u32(const void* p) {
    uint32_t a;
    asm("{ .reg .u64 t; cvta.to.shared.u64 t, %1; cvt.u32.u64 %0, t; }" : "=r"(a) : "l"(p));
    return a;
}
__device__ __forceinline__ void cp16(uint32_t dst, const void* src) {
    asm volatile("cp.async.cg.shared.global [%0], [%1], 16;" :: "r"(dst), "l"(src));
}
__device__ __forceinline__ void ldsm_x4(uint32_t* r, uint32_t addr) {
    asm volatile("ldmatrix.sync.aligned.m8n8.x4.shared.b16 {%0,%1,%2,%3}, [%4];"
                 : "=r"(r[0]), "=r"(r[1]), "=r"(r[2]), "=r"(r[3]) : "r"(addr));
}
__device__ __forceinline__ void ldsm_x2(uint32_t* r, uint32_t addr) {
    asm volatile("ldmatrix.sync.aligned.m8n8.x2.shared.b16 {%0,%1}, [%2];"
                 : "=r"(r[0]), "=r"(r[1]) : "r"(addr));
}
__device__ __forceinline__ void ldsm_x4_t(uint32_t* r, uint32_t addr) {
    asm volatile("ldmatrix.sync.aligned.m8n8.x4.trans.shared.b16 {%0,%1,%2,%3}, [%4];"
                 : "=r"(r[0]), "=r"(r[1]), "=r"(r[2]), "=r"(r[3]) : "r"(addr));
}
__device__ __forceinline__ void mma_f16(float* c, const uint32_t* a, const uint32_t* b) {
    asm volatile(
        "mma.sync.aligned.m16n8k16.row.col.f32.f16.f16.f32 "
        "{%0,%1,%2,%3}, {%4,%5,%6,%7}, {%8,%9}, {%0,%1,%2,%3};"
        : "+f"(c[0]), "+f"(c[1]), "+f"(c[2]), "+f"(c[3])
        : "r"(a[0]), "r"(a[1]), "r"(a[2]), "r"(a[3]), "r"(b[0]), "r"(b[1]));
}
#define CPWAIT(N) asm volatile("cp.async.wait_group %0;" :: "n"(N))
#define CPCOMMIT() asm volatile("cp.async.commit_group;" ::: "memory")

__device__ __forceinline__ void sts_zero16(uint32_t dst) {
    asm volatile("st.shared.v4.b32 [%0], {%1,%1,%1,%1};" :: "r"(dst), "r"(0) : "memory");
}
__device__ __forceinline__ void cp16z(uint32_t dst, const __half* src, bool valid) {
    if (valid) cp16(dst, src);
    else       sts_zero16(dst);
}

// ---------------------------------------------------------------------------
// Plain fp16 GEMM:  C = A @ B^T  (fp32 accum, OutT store)   [R13 winner]
// ---------------------------------------------------------------------------
#define GK       512
#define BK       64
#define NSTG     (GK / BK)          // 8
#define NBUF     3
#define PITCH    144
#define A_SZ     (128 * PITCH)      // 18432
#define STG_SZ   (2 * A_SZ)         // 36864
#define GEMM_SMEM (NBUF * STG_SZ)   // 110592

template <typename OutT>
__global__ __launch_bounds__(256, 2) void gemm_mma(
    const __half* __restrict__ A, const __half* __restrict__ B,
    OutT* __restrict__ C, int Ntot)
{
    extern __shared__ char smem[];
    const uint32_t sb = smem_u32(smem);
    const int tid  = threadIdx.x;
    const int wid  = tid >> 5;
    const int lane = tid & 31;
    const int bm = blockIdx.y * 128;
    const int bn = blockIdx.x * 128;
    const int warp_m = (wid >> 2) * 64;
    const int warp_n = (wid & 3) * 32;

    auto load_stage = [&](int s, int b) {
        const int k0 = s * BK;
        const uint32_t buf = sb + (uint32_t)b * STG_SZ;
        #pragma unroll
        for (int r = 0; r < 4; r++) {
            const int i   = tid + 256 * r;
            const int row = i >> 3;
            const int c16 = (i & 7) * 16;
            const uint32_t off = (uint32_t)(row * PITCH + c16);
            cp16(buf + off,        A + (size_t)(bm + row) * GK + k0 + (c16 >> 1));
            cp16(buf + A_SZ + off, B + (size_t)(bn + row) * GK + k0 + (c16 >> 1));
        }
        CPCOMMIT();
    };

    float acc[4][4][4];
    #pragma unroll
    for (int mi = 0; mi < 4; mi++)
        #pragma unroll
        for (int ni = 0; ni < 4; ni++)
            #pragma unroll
            for (int f = 0; f < 4; f++) acc[mi][ni][f] = 0.f;

    const uint32_t aLane = (uint32_t)((warp_m + (lane & 15)) * PITCH + ((lane >> 4) & 1) * 16);
    const uint32_t bLane4 = (uint32_t)((warp_n + ((lane >> 4) << 3) + (lane & 7)) * PITCH
                                       + ((lane >> 3) & 1) * 16);

    load_stage(0, 0);
    load_stage(1, 1);

    for (int s = 0; s < NSTG; s++) {
        const int b = s % NBUF;
        if (s + 1 < NSTG) CPWAIT(1);
        else              CPWAIT(0);
        __syncthreads();

        const uint32_t buf = sb + (uint32_t)b * STG_SZ;
        #pragma unroll
        for (int kk = 0; kk < 4; kk++) {
            const uint32_t ko = (uint32_t)(kk * 32);
            uint32_t ah[4][4], bh[4][2];
            #pragma unroll
            for (int mi = 0; mi < 4; mi++)
                ldsm_x4(ah[mi], buf + aLane + (uint32_t)(mi * 16 * PITCH) + ko);
            ldsm_x4(&bh[0][0], buf + A_SZ + bLane4 + ko);
            ldsm_x4(&bh[2][0], buf + A_SZ + bLane4 + (uint32_t)(16 * PITCH) + ko);
            #pragma unroll
            for (int mi = 0; mi < 4; mi++)
                #pragma unroll
                for (int ni = 0; ni < 4; ni++)
                    mma_f16(acc[mi][ni], ah[mi], bh[ni]);
        }

        if (s + 2 < NSTG) load_stage(s + 2, (s + 2) % NBUF);
    }

    const int er = lane >> 2;
    const int ec = (lane & 3) * 2;
    #pragma unroll
    for (int mi = 0; mi < 4; mi++) {
        #pragma unroll
        for (int ni = 0; ni < 4; ni++) {
            OutT* p0 = C + (size_t)(bm + warp_m + mi * 16 + er) * Ntot + bn + warp_n + ni * 8 + ec;
            if constexpr (sizeof(OutT) == 2) {
                *(__half2*)p0 = __floats2half2_rn(acc[mi][ni][0], acc[mi][ni][1]);
                *(__half2*)(p0 + (size_t)8 * Ntot) = __floats2half2_rn(acc[mi][ni][2], acc[mi][ni][3]);
            } else {
                *(float2*)p0                      = make_float2(acc[mi][ni][0], acc[mi][ni][1]);
                *(float2*)(p0 + (size_t)8 * Ntot) = make_float2(acc[mi][ni][2], acc[mi][ni][3]);
            }
        }
    }
}

// ---------------------------------------------------------------------------
// fused prep: x->fp16 + per-token width (blocks 0..8191, 2 tokens/block),
//             w_qkv^T (next 768), w_out^T (next 256)
// ---------------------------------------------------------------------------
__global__ __launch_bounds__(256) void prep_kernel(
    const float* __restrict__ x,     __half* __restrict__ xh,
    const float* __restrict__ wq,    __half* __restrict__ wqh,
    const float* __restrict__ wo,    __half* __restrict__ woh,
    const float* __restrict__ w_width, const float* __restrict__ b_width,
    float* __restrict__ width)
{
    const int bid = blockIdx.x;
    const int tid = threadIdx.x;
    if (bid < 8192) {
        const size_t i = ((size_t)bid * 256 + tid) * 4;
        float4 v = *(const float4*)(x + i);
        *(__half2*)(xh + i)     = __floats2half2_rn(v.x, v.y);
        *(__half2*)(xh + i + 2) = __floats2half2_rn(v.z, v.w);

        const float4 wv = ((const float4*)w_width)[tid & 127];
        float s = v.x * wv.x + v.y * wv.y + v.z * wv.z + v.w * wv.w;
        #pragma unroll
        for (int o = 16; o > 0; o >>= 1) s += __shfl_xor_sync(0xffffffffu, s, o);
        __shared__ float red[8];
        if ((tid & 31) == 0) red[tid >> 5] = s;
        __syncthreads();
        if (tid < 2) {
            const float tot = red[tid * 4] + red[tid * 4 + 1] + red[tid * 4 + 2] + red[tid * 4 + 3];
            width[bid * 2 + tid] =
                1.f / (1.f + expf(-(tot + b_width[0]))) * (float)(KWIN - 1) + 1.f;
        }
        return;
    }
    __shared__ float t[32][33];
    const float* w;  __half* wT;  int N, bx, by;
    if (bid < 8192 + 768) {
        w = wq; wT = wqh; N = 3 * CDIM;
        const int r = bid - 8192;
        bx = r % 48; by = r / 48;
    } else {
        w = wo; wT = woh; N = CDIM;
        const int r = bid - 8960;
        bx = r % 16; by = r / 16;
    }
    const int k0 = by * 32;
    const int n0 = bx * 32;
    const int tx = tid & 31, ty = tid >> 5;
    #pragma unroll
    for (int i = ty; i < 32; i += 8)
        t[i][tx] = w[(size_t)(k0 + i) * N + n0 + tx];
    __syncthreads();
    #pragma unroll
    for (int i = ty; i < 32; i += 8)
        wT[(size_t)(n0 + i) * CDIM + k0 + tx] = __float2half(t[tx][i]);
}

// ---------------------------------------------------------------------------
// MMA attention: 128 threads / 32 tokens.  Phase 1 triple-buffered (Q/K),
// CPWAIT(1) -> 2 compute windows per chunk load.  Q triple-buffer region is
// aliased with the V double-buffer (disjoint phases, barrier-separated).
// ---------------------------------------------------------------------------
#define ATB   32
#define AWIN  48
#define APIT  72          // halves per row (144 B)

__global__ __launch_bounds__(128) void attn_kernel(const float* __restrict__ width,
                                                   __half* __restrict__ att)
{
    // Q: 3 bufs x (32*72) halves == V: 2 bufs x (48*72) halves (same 13824 B)
    __shared__ __align__(128) __half shQV[3 * ATB * APIT];
    __shared__ __align__(128) __half shK[3][AWIN * APIT];   // 20736 B
    __shared__ __align__(128) float  shS[ATB * 48];         // 6144 B
    __shared__ __align__(128) __half shW[ATB * APIT];       // 4608 B
    __shared__ float shWidth[ATB];                          // total ~45.4 KB

    const int tid  = threadIdx.x;
    const int wid  = tid >> 5;
    const int lane = tid & 31;
    const int tok0 = blockIdx.x * ATB;
    const int l0   = tok0 & (LSEQ - 1);
    const int g0   = l0 - HALFK;
    const size_t gbase = (size_t)(tok0 >> 13) * LSEQ;

    const __half* qkv = g_qkvh;
    const uint32_t qvb0 = smem_u32(shQV);
    const uint32_t wb = smem_u32(shW);

    auto load_qk = [&](int kc, int b) {
        const int k0 = kc * 64;
        const uint32_t qb = qvb0 + (uint32_t)b * (ATB * APIT * 2);
        const uint32_t kb = smem_u32(shK[b]);
        #pragma unroll
        for (int r = 0; r < 2; r++) {
            const int i = tid + 128 * r;
            const int row = i >> 3;
            const int c16 = (i & 7) * 16;
            cp16(qb + (uint32_t)(row * 144 + c16),
                 qkv + (size_t)(tok0 + row) * 3 * CDIM + k0 + (c16 >> 1));
        }
        #pragma unroll
        for (int r = 0; r < 3; r++) {
            const int i = tid + 128 * r;
            const int row = i >> 3;
            const int c16 = (i & 7) * 16;
            const int gl = g0 + row;
            cp16z(kb + (uint32_t)(row * 144 + c16),
                  qkv + ((size_t)(gbase + gl) * 3 + 1) * CDIM + k0 + (c16 >> 1),
                  (gl >= 0 && gl < LSEQ));
        }
        CPCOMMIT();
    };
    auto load_v = [&](int nc, int b) {
        const int ch0 = nc * 64;
        const uint32_t vb = qvb0 + (uint32_t)b * (AWIN * APIT * 2);
        #pragma unroll
        for (int r = 0; r < 3; r++) {
            const int i = tid + 128 * r;
            const int row = i >> 3;
            const int c16 = (i & 7) * 16;
            const int gl = g0 + row;
            cp16z(vb + (uint32_t)(row * 144 + c16),
                  qkv + ((size_t)(gbase + gl) * 3 + 2) * CDIM + ch0 + (c16 >> 1),
                  (gl >= 0 && gl < LSEQ));
        }
        CPCOMMIT();
    };

    load_qk(0, 0);
    load_qk(1, 1);
    if (tid < ATB) shWidth[tid] = width[tok0 + tid];

    // ---- phase 1: scores S = Q @ K^T (triple buffered, 2-deep pipeline) ----
    const int m0 = (wid >> 1) * 16;
    const int n0 = (wid & 1) * 24;
    const uint32_t aOffQ = (uint32_t)((m0 + (lane & 15)) * 144 + ((lane >> 4) & 1) * 16);
    const uint32_t bOff4 = (uint32_t)((n0 + ((lane >> 4) << 3) + (lane & 7)) * 144
                                      + ((lane >> 3) & 1) * 16);
    const uint32_t bOff2 = (uint32_t)((n0 + 16 + (lane & 7)) * 144 + ((lane >> 3) & 1) * 16);

    float s[3][4];
    #pragma unroll
    for (int f = 0; f < 3; f++)
        #pragma unroll
        for (int j = 0; j < 4; j++) s[f][j] = 0.f;

    for (int kc = 0; kc < 8; kc++) {
        const int b = kc % 3;
        if (kc < 7) CPWAIT(1);
        else        CPWAIT(0);
        __syncthreads();
        // target buf (kc+2)%3 == (kc-1)%3: consumed at iter kc-1, barrier-covered
        if (kc + 2 < 8) load_qk(kc + 2, (kc + 2) % 3);

        const uint32_t qb = qvb0 + (uint32_t)b * (ATB * APIT * 2);
        const uint32_t kb = smem_u32(shK[b]);
        #pragma unroll
        for (int ks = 0; ks < 4; ks++) {
            const uint32_t ko = (uint32_t)(ks * 32);
            uint32_t a[4], b0[4], b2[2];
            ldsm_x4(a, qb + aOffQ + ko);
            ldsm_x4(b0, kb + bOff4 + ko);
            ldsm_x2(b2, kb + bOff2 + ko);
            mma_f16(s[0], a, b0);
            mma_f16(s[1], a, b0 + 2);
            mma_f16(s[2], a, b2);
        }
    }

    // scores -> shS, zero shW (does not touch the Q/V union)
    #pragma unroll
    for (int f = 0; f < 3; f++) {
        const int r = m0 + (lane >> 2);
        const int c = n0 + f * 8 + (lane & 3) * 2;
        shS[r * 48 + c]           = s[f][0];
        shS[r * 48 + c + 1]       = s[f][1];
        shS[(r + 8) * 48 + c]     = s[f][2];
        shS[(r + 8) * 48 + c + 1] = s[f][3];
    }
    #pragma unroll
    for (int i = tid; i < ATB * APIT / 2; i += 128)
        ((uint32_t*)shW)[i] = 0;
    __syncthreads();          // all warps done reading Q bufs -> V may reuse them

    // V chunks 0 and 1 load during the softmax
    load_v(0, 0);
    load_v(1, 1);

    // ---- phase 2: mask + softmax (one thread per token) ----
    if (tid < ATB) {
        const float width_t = shWidth[tid];
        const float scale = 0.044194173824159216f;
        float p[KWIN];
        float mx = -1e30f;
        #pragma unroll
        for (int j = 0; j < KWIN; j++) {
            const float rel = fabsf((float)j - (float)HALFK);
            const float m = 1.f / (1.f + expf(-(width_t - rel) * 5.f));
            const float v = shS[tid * 48 + tid + j] * scale - (1.f - m) * 10000.f;
            p[j] = v;
            mx = fmaxf(mx, v);
        }
        float d = 0.f;
        #pragma unroll
        for (int j = 0; j < KWIN; j++) { p[j] = expf(p[j] - mx); d += p[j]; }
        const float inv = 1.f / d;
        #pragma unroll
        for (int j = 0; j < KWIN; j++)
            shW[tid * APIT + tid + j] = __float2half(p[j] * inv);
    }

    // ---- phase 3: att = W @ V + v_self (V double buffered) ----
    const int n0c = (wid & 1) * 32;
    const uint32_t aLw = wb + (uint32_t)((m0 + (lane & 15)) * 144 + ((lane >> 4) & 1) * 16);
    const int tg = lane >> 3, tl = lane & 7;

    for (int nc = 0; nc < 8; nc++) {
        const int b = nc & 1;
        if (nc == 0) CPWAIT(1);       // V0 done; V1 still in flight
        else         CPWAIT(0);
        __syncthreads();
        if (nc >= 1 && nc + 1 < 8) load_v(nc + 1, (nc + 1) & 1);

        const int ch0 = nc * 64;
        const uint32_t vb = qvb0 + (uint32_t)b * (AWIN * APIT * 2);
        const __half* shVc = shQV + (size_t)b * (AWIN * APIT);

        float o[4][4];
        #pragma unroll
        for (int f = 0; f < 4; f++)
            #pragma unroll
            for (int j = 0; j < 4; j++) o[f][j] = 0.f;

        #pragma unroll
        for (int ks = 0; ks < 3; ks++) {
            uint32_t a[4], bt[8];
            ldsm_x4(a, aLw + (uint32_t)(ks * 32));
            #pragma unroll
            for (int h = 0; h < 2; h++) {
                const int row = ks * 16 + (tg & 1) * 8 + tl;
                const int col = n0c + h * 16 + (tg >> 1) * 8;
                ldsm_x4_t(bt + h * 4, vb + (uint32_t)(row * 144 + col * 2));
            }
            mma_f16(o[0], a, bt + 0);
            mma_f16(o[1], a, bt + 2);
            mma_f16(o[2], a, bt + 4);
            mma_f16(o[3], a, bt + 6);
        }

        #pragma unroll
        for (int f = 0; f < 4; f++) {
            const int rr = m0 + (lane >> 2);
            const int cc = n0c + f * 8 + (lane & 3) * 2;
            const float2 v0 = __half22float2(*(const __half2*)(shVc + (rr + 8) * APIT + cc));
            const float2 v1 = __half22float2(*(const __half2*)(shVc + (rr + 16) * APIT + cc));
            *(__half2*)(att + (size_t)(tok0 + rr) * CDIM + ch0 + cc) =
                __floats2half2_rn(o[f][0] + v0.x, o[f][1] + v0.y);
            *(__half2*)(att + (size_t)(tok0 + rr + 8) * CDIM + ch0 + cc) =
                __floats2half2_rn(o[f][2] + v1.x, o[f][3] + v1.y);
        }
    }
}

// ---------------------------------------------------------------------------
extern "C" void kernel_launch(void* const* d_in, const int* in_sizes, int n_in,
                              void* d_out, int out_size)
{
    const float* x       = (const float*)d_in[0];
    const float* w_qkv   = (const float*)d_in[1];
    const float* w_width = (const float*)d_in[2];
    const float* b_width = (const float*)d_in[3];
    const float* w_out   = (const float*)d_in[4];
    float* out = (float*)d_out;

    __half* qkvh; cudaGetSymbolAddress((void**)&qkvh, g_qkvh);
    __half* xh;   cudaGetSymbolAddress((void**)&xh,   g_xh);
    __half* ah;   cudaGetSymbolAddress((void**)&ah,   g_ah);
    __half* wqh;  cudaGetSymbolAddress((void**)&wqh,  g_wqh);
    __half* woh;  cudaGetSymbolAddress((void**)&woh,  g_woh);
    float*  wdt;  cudaGetSymbolAddress((void**)&wdt,  g_width);

    cudaFuncSetAttribute(gemm_mma<__half>, cudaFuncAttributeMaxDynamicSharedMemorySize, GEMM_SMEM);
    cudaFuncSetAttribute(gemm_mma<float>,  cudaFuncAttributeMaxDynamicSharedMemorySize, GEMM_SMEM);

    // 0) fused prep: x->fp16 + widths + both weight transposes
    prep_kernel<<<8192 + 768 + 256, 256>>>(x, xh, w_qkv, wqh, w_out, woh,
                                           w_width, b_width, wdt);

    // 1) qkv = x @ w_qkv   (fp16 in, fp16 out)
    {
        dim3 grid(3 * CDIM / 128, NTOK / 128);
        gemm_mma<__half><<<grid, 256, GEMM_SMEM>>>(xh, wqh, qkvh, 3 * CDIM);
    }

    // 2) MMA windowed attention -> att (fp16)
    attn_kernel<<<NTOK / ATB, 128>>>(wdt, ah);

    // 3) out = att @ w_out  (fp16 in, fp32 out)
    {
        dim3 grid(CDIM / 128, NTOK / 128);
        gemm_mma<float><<<grid, 256, GEMM_SMEM>>>(ah, woh, out, CDIM);
    }
}